// round 9
// baseline (speedup 1.0000x reference)
#include <cuda_runtime.h>
#include <cstdint>

#define D_IN  2048
#define H1    128
#define H2    64
#define F1    32
#define BATCH 64
#define TSEQ  512
#define MTOT  (BATCH * TSEQ)   // 32768

typedef unsigned long long ull;

// ---- static device scratch (allocation-free) ----
__device__ float g_xp1[MTOT * H1];                          // 16 MB
__device__ __align__(16) unsigned short g_whi[H1 * D_IN];   // W_ih1 bf16 hi
__device__ __align__(16) unsigned short g_wlo[H1 * D_IN];   // W_ih1 bf16 lo

// ---------------- packed f32x2 helpers ----------------
__device__ __forceinline__ void fma2(ull &acc, ull a, ull b) {
    asm("fma.rn.f32x2 %0, %1, %2, %0;" : "+l"(acc) : "l"(a), "l"(b));
}
__device__ __forceinline__ void add2(ull &d, ull a, ull b) {
    asm("add.rn.f32x2 %0, %1, %2;" : "=l"(d) : "l"(a), "l"(b));
}
__device__ __forceinline__ float lo32(ull v) { return __uint_as_float((unsigned)v); }
__device__ __forceinline__ float hi32(ull v) { return __uint_as_float((unsigned)(v >> 32)); }

__device__ __forceinline__ float fast_tanh(float x) {
    float e = __expf(2.0f * x);
    return 1.0f - __fdividef(2.0f, e + 1.0f);
}

__device__ __forceinline__ uint32_t smem_u32(const void* p) {
    uint32_t a;
    asm("{ .reg .u64 t; cvta.to.shared.u64 t, %1; cvt.u32.u64 %0, t; }" : "=r"(a) : "l"(p));
    return a;
}

// ---------------- mma.sync / ldmatrix primitives (legal on compute_103) ----------------
__device__ __forceinline__ void mma_bf16(float4 &d, uint4 a, uint32_t b0, uint32_t b1) {
    asm volatile(
        "mma.sync.aligned.m16n8k16.row.col.f32.bf16.bf16.f32 "
        "{%0,%1,%2,%3}, {%4,%5,%6,%7}, {%8,%9}, {%0,%1,%2,%3};"
        : "+f"(d.x), "+f"(d.y), "+f"(d.z), "+f"(d.w)
        : "r"(a.x), "r"(a.y), "r"(a.z), "r"(a.w), "r"(b0), "r"(b1));
}
__device__ __forceinline__ uint4 ldsm4(uint32_t addr) {
    uint4 v;
    asm volatile("ldmatrix.sync.aligned.m8n8.x4.shared.b16 {%0,%1,%2,%3}, [%4];"
        : "=r"(v.x), "=r"(v.y), "=r"(v.z), "=r"(v.w) : "r"(addr));
    return v;
}

// split one fp32 float4 into hi/lo bf16x2 pairs
__device__ __forceinline__ void cvt_split(float4 v, uint2& hi, uint2& lo) {
    uint32_t h01, h23, l01, l23;
    asm("cvt.rn.bf16x2.f32 %0, %1, %2;" : "=r"(h01) : "f"(v.y), "f"(v.x));
    asm("cvt.rn.bf16x2.f32 %0, %1, %2;" : "=r"(h23) : "f"(v.w), "f"(v.z));
    float b0 = __uint_as_float(h01 << 16);
    float b1 = __uint_as_float(h01 & 0xffff0000u);
    float b2 = __uint_as_float(h23 << 16);
    float b3 = __uint_as_float(h23 & 0xffff0000u);
    asm("cvt.rn.bf16x2.f32 %0, %1, %2;" : "=r"(l01) : "f"(v.y - b1), "f"(v.x - b0));
    asm("cvt.rn.bf16x2.f32 %0, %1, %2;" : "=r"(l23) : "f"(v.w - b3), "f"(v.z - b2));
    hi = make_uint2(h01, h23);
    lo = make_uint2(l01, l23);
}

// =====================================================================================
// Kernel 0: pre-split W_ih1 (128x2048 fp32) into bf16 hi/lo globals. 65536 float4s.
// =====================================================================================
__global__ void __launch_bounds__(256, 1) convert_w_kernel(const float* __restrict__ W)
{
    int idx = blockIdx.x * 256 + threadIdx.x;        // grid 256 -> 65536 threads
    float4 v = ((const float4*)W)[idx];
    uint2 hi, lo;
    cvt_split(v, hi, lo);
    ((uint2*)g_whi)[idx] = hi;
    ((uint2*)g_wlo)[idx] = lo;
}

// =====================================================================================
// Kernel 1: xp1 = x @ W_ih1^T + b_ih1 via mma.sync bf16 3-term split (R6-proven, 1 CTA/SM).
// =====================================================================================
#define PITCH  80
#define NSTG   64
#define ATILE  (128 * PITCH)
#define BUFSZ  (4 * ATILE)
#define GSMEM  (512 + 2 * BUFSZ)  // 82432 B

__device__ __forceinline__ void stage_store(char* buf, uint32_t off,
                                            const float4* ra, const uint4* rbh, const uint4* rbl)
{
    char* Ahi = buf;
    char* Alo = buf + ATILE;
    char* Bhi = buf + 2 * ATILE;
    char* Blo = buf + 3 * ATILE;
#pragma unroll
    for (int f = 0; f < 4; ++f) {
        uint2 hi, lo;
        cvt_split(ra[f], hi, lo);
        *(uint2*)(Ahi + off + f * 8) = hi;
        *(uint2*)(Alo + off + f * 8) = lo;
    }
    *(uint4*)(Bhi + off)      = rbh[0];
    *(uint4*)(Bhi + off + 16) = rbh[1];
    *(uint4*)(Blo + off)      = rbl[0];
    *(uint4*)(Blo + off + 16) = rbl[1];
}

__global__ void __launch_bounds__(256, 1) gemm_mma_kernel(
    const float* __restrict__ X, const float* __restrict__ bias)
{
    extern __shared__ __align__(16) char smem[];
    float* biasS = (float*)smem;
    char* bufb = smem + 512;
    const uint32_t sb = smem_u32(bufb);

    const int tid = threadIdx.x, lane = tid & 31, w = tid >> 5;
    const int wm = w & 3, wn = w >> 2;
    const int mBase = blockIdx.x * 128;

    if (tid < 128) biasS[tid] = bias[tid];

    const int row = tid >> 1, half = tid & 1;
    const float* Arow = X + (size_t)(mBase + row) * D_IN + half * 16;
    const char* BhiG = (const char*)g_whi + (size_t)row * D_IN * 2 + half * 32;
    const char* BloG = (const char*)g_wlo + (size_t)row * D_IN * 2 + half * 32;
    const uint32_t sts_off = (uint32_t)(row * PITCH + half * 32);

    const uint32_t aoff = (uint32_t)((wm * 32 + (lane & 15)) * PITCH + (lane >> 4) * 16);
    const uint32_t boff = (uint32_t)((wn * 64 + (lane & 7) + ((lane >> 4) & 1) * 8) * PITCH
                                     + ((lane >> 3) & 1) * 16);

    float4 acc[2][8];
#pragma unroll
    for (int mi = 0; mi < 2; ++mi)
#pragma unroll
        for (int ni = 0; ni < 8; ++ni) acc[mi][ni] = make_float4(0.f, 0.f, 0.f, 0.f);

    float4 ra[4];
    uint4 rbh[2], rbl[2];
#pragma unroll
    for (int f = 0; f < 4; ++f) ra[f] = *(const float4*)(Arow + f * 4);
    rbh[0] = *(const uint4*)(BhiG);
    rbh[1] = *(const uint4*)(BhiG + 16);
    rbl[0] = *(const uint4*)(BloG);
    rbl[1] = *(const uint4*)(BloG + 16);
    stage_store(bufb, sts_off, ra, rbh, rbl);
    __syncthreads();

    for (int i = 0; i < NSTG; ++i) {
        const int cur = i & 1;
        if (i + 1 < NSTG) {
            const int ko = (i + 1) * 32;
#pragma unroll
            for (int f = 0; f < 4; ++f) ra[f] = *(const float4*)(Arow + ko + f * 4);
            rbh[0] = *(const uint4*)(BhiG + ko * 2);
            rbh[1] = *(const uint4*)(BhiG + ko * 2 + 16);
            rbl[0] = *(const uint4*)(BloG + ko * 2);
            rbl[1] = *(const uint4*)(BloG + ko * 2 + 16);
        }

        const uint32_t Ahi = sb + cur * BUFSZ;
        const uint32_t Alo = Ahi + ATILE;
        const uint32_t Bhi = Ahi + 2 * ATILE;
        const uint32_t Blo = Ahi + 3 * ATILE;

#pragma unroll
        for (int kc = 0; kc < 2; ++kc) {
            const uint32_t kb = kc * 32;

            uint4 ah0 = ldsm4(Ahi + aoff + kb);
            uint4 ah1 = ldsm4(Ahi + aoff + 16 * PITCH + kb);
            uint4 bh0 = ldsm4(Bhi + boff + kb);
            uint4 bh1 = ldsm4(Bhi + boff + 16 * PITCH + kb);
            uint4 bh2 = ldsm4(Bhi + boff + 32 * PITCH + kb);
            uint4 bh3 = ldsm4(Bhi + boff + 48 * PITCH + kb);

            mma_bf16(acc[0][0], ah0, bh0.x, bh0.y);
            mma_bf16(acc[0][1], ah0, bh0.z, bh0.w);
            mma_bf16(acc[0][2], ah0, bh1.x, bh1.y);
            mma_bf16(acc[0][3], ah0, bh1.z, bh1.w);
            mma_bf16(acc[0][4], ah0, bh2.x, bh2.y);
            mma_bf16(acc[0][5], ah0, bh2.z, bh2.w);
            mma_bf16(acc[0][6], ah0, bh3.x, bh3.y);
            mma_bf16(acc[0][7], ah0, bh3.z, bh3.w);
            mma_bf16(acc[1][0], ah1, bh0.x, bh0.y);
            mma_bf16(acc[1][1], ah1, bh0.z, bh0.w);
            mma_bf16(acc[1][2], ah1, bh1.x, bh1.y);
            mma_bf16(acc[1][3], ah1, bh1.z, bh1.w);
            mma_bf16(acc[1][4], ah1, bh2.x, bh2.y);
            mma_bf16(acc[1][5], ah1, bh2.z, bh2.w);
            mma_bf16(acc[1][6], ah1, bh3.x, bh3.y);
            mma_bf16(acc[1][7], ah1, bh3.z, bh3.w);

            uint4 bl0 = ldsm4(Blo + boff + kb);
            uint4 bl1 = ldsm4(Blo + boff + 16 * PITCH + kb);
            uint4 bl2 = ldsm4(Blo + boff + 32 * PITCH + kb);
            uint4 bl3 = ldsm4(Blo + boff + 48 * PITCH + kb);

            mma_bf16(acc[0][0], ah0, bl0.x, bl0.y);
            mma_bf16(acc[0][1], ah0, bl0.z, bl0.w);
            mma_bf16(acc[0][2], ah0, bl1.x, bl1.y);
            mma_bf16(acc[0][3], ah0, bl1.z, bl1.w);
            mma_bf16(acc[0][4], ah0, bl2.x, bl2.y);
            mma_bf16(acc[0][5], ah0, bl2.z, bl2.w);
            mma_bf16(acc[0][6], ah0, bl3.x, bl3.y);
            mma_bf16(acc[0][7], ah0, bl3.z, bl3.w);
            mma_bf16(acc[1][0], ah1, bl0.x, bl0.y);
            mma_bf16(acc[1][1], ah1, bl0.z, bl0.w);
            mma_bf16(acc[1][2], ah1, bl1.x, bl1.y);
            mma_bf16(acc[1][3], ah1, bl1.z, bl1.w);
            mma_bf16(acc[1][4], ah1, bl2.x, bl2.y);
            mma_bf16(acc[1][5], ah1, bl2.z, bl2.w);
            mma_bf16(acc[1][6], ah1, bl3.x, bl3.y);
            mma_bf16(acc[1][7], ah1, bl3.z, bl3.w);

            uint4 al0 = ldsm4(Alo + aoff + kb);
            uint4 al1 = ldsm4(Alo + aoff + 16 * PITCH + kb);

            mma_bf16(acc[0][0], al0, bh0.x, bh0.y);
            mma_bf16(acc[0][1], al0, bh0.z, bh0.w);
            mma_bf16(acc[0][2], al0, bh1.x, bh1.y);
            mma_bf16(acc[0][3], al0, bh1.z, bh1.w);
            mma_bf16(acc[0][4], al0, bh2.x, bh2.y);
            mma_bf16(acc[0][5], al0, bh2.z, bh2.w);
            mma_bf16(acc[0][6], al0, bh3.x, bh3.y);
            mma_bf16(acc[0][7], al0, bh3.z, bh3.w);
            mma_bf16(acc[1][0], al1, bh0.x, bh0.y);
            mma_bf16(acc[1][1], al1, bh0.z, bh0.w);
            mma_bf16(acc[1][2], al1, bh1.x, bh1.y);
            mma_bf16(acc[1][3], al1, bh1.z, bh1.w);
            mma_bf16(acc[1][4], al1, bh2.x, bh2.y);
            mma_bf16(acc[1][5], al1, bh2.z, bh2.w);
            mma_bf16(acc[1][6], al1, bh3.x, bh3.y);
            mma_bf16(acc[1][7], al1, bh3.z, bh3.w);
        }

        if (i + 1 < NSTG) stage_store(bufb + (cur ^ 1) * BUFSZ, sts_off, ra, rbh, rbl);
        __syncthreads();
    }

    const int row0 = mBase + wm * 32 + (lane >> 2);
    const int cb = wn * 64 + (lane & 3) * 2;
#pragma unroll
    for (int mi = 0; mi < 2; ++mi)
#pragma unroll
        for (int ni = 0; ni < 8; ++ni) {
            const int r = row0 + mi * 16;
            const int c = cb + ni * 8;
            float2 v;
            v.x = acc[mi][ni].x + biasS[c];
            v.y = acc[mi][ni].y + biasS[c + 1];
            *(float2*)(g_xp1 + (size_t)r * H1 + c) = v;
            v.x = acc[mi][ni].z + biasS[c];
            v.y = acc[mi][ni].w + biasS[c + 1];
            *(float2*)(g_xp1 + (size_t)(r + 8) * H1 + c) = v;
        }
}

// =====================================================================================
// Kernel 2: SERIAL dual-RNN scan + FC head. One CTA per batch, 256 threads, all threads
// run both layers. Weights fully register-resident. 2 plain __syncthreads per step
// (replaces 4 named-barrier events of the pipelined design).
//   L1: thread (2i+half) computes half of dot for h1[i]; shfl-xor-1 reduce.
//   L2: thread (4j+q) computes quarter of dot for h2[j]; shfl-xor-1,2 reduce.
// =====================================================================================
__global__ void __launch_bounds__(256, 1) rnn_scan_kernel(
    const float* __restrict__ W_hh1, const float* __restrict__ b_hh1,
    const float* __restrict__ W_ih2, const float* __restrict__ W_hh2,
    const float* __restrict__ b_ih2, const float* __restrict__ b_hh2,
    const float* __restrict__ W_fc1, const float* __restrict__ b_fc1,
    const float* __restrict__ W_fc2, const float* __restrict__ b_fc2,
    float* __restrict__ out)
{
    __shared__ __align__(16) float h1buf[2][H1];
    __shared__ __align__(16) float h2buf[2][H2];

    const int tid = threadIdx.x;
    const int bb = blockIdx.x;
    const int i = tid >> 1, half = tid & 1;   // L1 role
    const int j = tid >> 2, q = tid & 3;      // L2 role

    // L1 weights: W_hh1[i, half*64 .. +64) as 32 packed pairs (64 regs)
    ull w1p[32];
#pragma unroll
    for (int k = 0; k < 32; ++k)
        w1p[k] = *(const ull*)(W_hh1 + i * H1 + half * 64 + 2 * k);
    const float bias1 = b_hh1[i];

    // L2 weights: W_ih2[j, q*32 .. +32) (16 pairs) + W_hh2[j, q*16 .. +16) (8 pairs)
    ull wip[16];
#pragma unroll
    for (int k = 0; k < 16; ++k)
        wip[k] = *(const ull*)(W_ih2 + j * H1 + q * 32 + 2 * k);
    ull whp[8];
#pragma unroll
    for (int k = 0; k < 8; ++k)
        whp[k] = *(const ull*)(W_hh2 + j * H2 + q * 16 + 2 * k);
    const float bias2 = __ldg(b_ih2 + j) + __ldg(b_hh2 + j);

    if (tid < H1) h1buf[0][tid] = 0.f;        // h1(-1), read at t=0
    if (tid < H2) h2buf[0][tid] = 0.f;        // h2(-1)

    const float* xp = g_xp1 + (size_t)bb * TSEQ * H1;
    float xv = __ldg(xp + i);                 // xp1(t=0)
    __syncthreads();

    for (int t = 0; t < TSEQ; ++t) {
        const int p = t & 1;

        // ---- layer 1: dot(W_hh1[i, half-slice], h1_old) ----
        const ulonglong2* hp = (const ulonglong2*)(h1buf[p] + half * 64);
        ull a0 = 0, a1 = 0, a2 = 0, a3 = 0;
#pragma unroll
        for (int k = 0; k < 8; ++k) {
            ulonglong2 h01 = hp[2 * k];
            ulonglong2 h23 = hp[2 * k + 1];
            fma2(a0, w1p[4 * k + 0], h01.x);
            fma2(a1, w1p[4 * k + 1], h01.y);
            fma2(a2, w1p[4 * k + 2], h23.x);
            fma2(a3, w1p[4 * k + 3], h23.y);
        }

        // prefetch next xp1 while the dot chain drains
        float xnext = 0.f;
        if (t + 1 < TSEQ) xnext = __ldg(xp + (t + 1) * H1 + i);

        ull s01, s23, sall;
        add2(s01, a0, a1);
        add2(s23, a2, a3);
        add2(sall, s01, s23);
        float dot = lo32(sall) + hi32(sall);
        dot += __shfl_xor_sync(0xffffffffu, dot, 1);
        if (!half) h1buf[p ^ 1][i] = fast_tanh(xv + bias1 + dot);
        __syncthreads();                       // h1(t) visible

        // ---- layer 2: W_ih2 @ h1_new + W_hh2 @ h2_old ----
        const ulonglong2* hn = (const ulonglong2*)(h1buf[p ^ 1] + q * 32);
        const ulonglong2* go = (const ulonglong2*)(h2buf[p] + q * 16);
        ull c0 = 0, c1 = 0, c2 = 0, c3 = 0;
#pragma unroll
        for (int m = 0; m < 4; ++m) {
            ulonglong2 h01 = hn[2 * m];
            ulonglong2 h23 = hn[2 * m + 1];
            fma2(c0, wip[4 * m + 0], h01.x);
            fma2(c1, wip[4 * m + 1], h01.y);
            fma2(c2, wip[4 * m + 2], h23.x);
            fma2(c3, wip[4 * m + 3], h23.y);
        }
#pragma unroll
        for (int m = 0; m < 2; ++m) {
            ulonglong2 g01 = go[2 * m];
            ulonglong2 g23 = go[2 * m + 1];
            fma2(c0, whp[4 * m + 0], g01.x);
            fma2(c1, whp[4 * m + 1], g01.y);
            fma2(c2, whp[4 * m + 2], g23.x);
            fma2(c3, whp[4 * m + 3], g23.y);
        }
        ull t01, t23, tall;
        add2(t01, c0, c1);
        add2(t23, c2, c3);
        add2(tall, t01, t23);
        float d = lo32(tall) + hi32(tall);
        d += __shfl_xor_sync(0xffffffffu, d, 1);
        d += __shfl_xor_sync(0xffffffffu, d, 2);
        if (q == 0) h2buf[p ^ 1][j] = fast_tanh(d + bias2);
        __syncthreads();                       // h2(t) visible; buffers safe to rotate

        xv = xnext;
    }

    // ---- FC head: final h2 = h2(511) lives in h2buf[0] (511^1 -> buf 0) ----
    if (tid < F1) {
        const float* hf = h2buf[0];
        float acc = b_fc1[tid];
#pragma unroll
        for (int k = 0; k < H2; ++k) acc = fmaf(W_fc1[tid * H2 + k], hf[k], acc);
        float r = fmaxf(acc, 0.f) * W_fc2[tid];
#pragma unroll
        for (int sft = 16; sft > 0; sft >>= 1) r += __shfl_xor_sync(0xffffffffu, r, sft);
        if (tid == 0) out[bb] = r + b_fc2[0];
    }
}

// =====================================================================================
extern "C" void kernel_launch(void* const* d_in, const int* in_sizes, int n_in,
                              void* d_out, int out_size)
{
    const float* x     = (const float*)d_in[0];
    const float* W_ih1 = (const float*)d_in[1];
    const float* W_hh1 = (const float*)d_in[2];
    const float* b_ih1 = (const float*)d_in[3];
    const float* b_hh1 = (const float*)d_in[4];
    const float* W_ih2 = (const float*)d_in[5];
    const float* W_hh2 = (const float*)d_in[6];
    const float* b_ih2 = (const float*)d_in[7];
    const float* b_hh2 = (const float*)d_in[8];
    const float* W_fc1 = (const float*)d_in[9];
    const float* b_fc1 = (const float*)d_in[10];
    const float* W_fc2 = (const float*)d_in[11];
    const float* b_fc2 = (const float*)d_in[12];
    float* out = (float*)d_out;

    convert_w_kernel<<<256, 256>>>(W_ih1);
    cudaFuncSetAttribute(gemm_mma_kernel, cudaFuncAttributeMaxDynamicSharedMemorySize, GSMEM);
    gemm_mma_kernel<<<MTOT / 128, 256, GSMEM>>>(x, b_ih1);
    rnn_scan_kernel<<<BATCH, 256>>>(W_hh1, b_hh1, W_ih2, W_hh2, b_ih2, b_hh2,
                                    W_fc1, b_fc1, W_fc2, b_fc2, out);
}

// round 10
// speedup vs baseline: 1.4843x; 1.4843x over previous
#include <cuda_runtime.h>
#include <cstdint>

#define D_IN  2048
#define H1    128
#define H2    64
#define F1    32
#define BATCH 64
#define TSEQ  512
#define MTOT  (BATCH * TSEQ)   // 32768

typedef unsigned long long ull;

// ---- static device scratch (allocation-free) ----
__device__ float g_xp1[MTOT * H1];                          // 16 MB
__device__ __align__(16) unsigned short g_whi[H1 * D_IN];   // W_ih1 bf16 hi
__device__ __align__(16) unsigned short g_wlo[H1 * D_IN];   // W_ih1 bf16 lo

// ---------------- packed f32x2 helpers (scan) ----------------
__device__ __forceinline__ void fma2(ull &acc, ull a, ull b) {
    asm("fma.rn.f32x2 %0, %1, %2, %0;" : "+l"(acc) : "l"(a), "l"(b));
}
__device__ __forceinline__ void add2(ull &d, ull a, ull b) {
    asm("add.rn.f32x2 %0, %1, %2;" : "=l"(d) : "l"(a), "l"(b));
}
__device__ __forceinline__ float lo32(ull v) { return __uint_as_float((unsigned)v); }
__device__ __forceinline__ float hi32(ull v) { return __uint_as_float((unsigned)(v >> 32)); }

__device__ __forceinline__ float fast_tanh(float x) {
    float e = __expf(2.0f * x);
    return 1.0f - __fdividef(2.0f, e + 1.0f);
}

#define BAR_SYNC(id, n)   asm volatile("bar.sync %0, %1;"   :: "r"(id), "r"(n) : "memory")
#define BAR_ARRIVE(id, n) asm volatile("bar.arrive %0, %1;" :: "r"(id), "r"(n) : "memory")

__device__ __forceinline__ uint32_t smem_u32(const void* p) {
    uint32_t a;
    asm("{ .reg .u64 t; cvta.to.shared.u64 t, %1; cvt.u32.u64 %0, t; }" : "=r"(a) : "l"(p));
    return a;
}

// ---------------- mma.sync / ldmatrix primitives (legal on compute_103) ----------------
__device__ __forceinline__ void mma_bf16(float4 &d, uint4 a, uint32_t b0, uint32_t b1) {
    asm volatile(
        "mma.sync.aligned.m16n8k16.row.col.f32.bf16.bf16.f32 "
        "{%0,%1,%2,%3}, {%4,%5,%6,%7}, {%8,%9}, {%0,%1,%2,%3};"
        : "+f"(d.x), "+f"(d.y), "+f"(d.z), "+f"(d.w)
        : "r"(a.x), "r"(a.y), "r"(a.z), "r"(a.w), "r"(b0), "r"(b1));
}
__device__ __forceinline__ uint4 ldsm4(uint32_t addr) {
    uint4 v;
    asm volatile("ldmatrix.sync.aligned.m8n8.x4.shared.b16 {%0,%1,%2,%3}, [%4];"
        : "=r"(v.x), "=r"(v.y), "=r"(v.z), "=r"(v.w) : "r"(addr));
    return v;
}

// split one fp32 float4 into hi/lo bf16x2 pairs
__device__ __forceinline__ void cvt_split(float4 v, uint2& hi, uint2& lo) {
    uint32_t h01, h23, l01, l23;
    asm("cvt.rn.bf16x2.f32 %0, %1, %2;" : "=r"(h01) : "f"(v.y), "f"(v.x));
    asm("cvt.rn.bf16x2.f32 %0, %1, %2;" : "=r"(h23) : "f"(v.w), "f"(v.z));
    float b0 = __uint_as_float(h01 << 16);
    float b1 = __uint_as_float(h01 & 0xffff0000u);
    float b2 = __uint_as_float(h23 << 16);
    float b3 = __uint_as_float(h23 & 0xffff0000u);
    asm("cvt.rn.bf16x2.f32 %0, %1, %2;" : "=r"(l01) : "f"(v.y - b1), "f"(v.x - b0));
    asm("cvt.rn.bf16x2.f32 %0, %1, %2;" : "=r"(l23) : "f"(v.w - b3), "f"(v.z - b2));
    hi = make_uint2(h01, h23);
    lo = make_uint2(l01, l23);
}

// =====================================================================================
// Kernel 0: pre-split W_ih1 (128x2048 fp32) into bf16 hi/lo globals. 65536 float4s.
// =====================================================================================
__global__ void __launch_bounds__(256, 1) convert_w_kernel(const float* __restrict__ W)
{
    int idx = blockIdx.x * 256 + threadIdx.x;
    float4 v = ((const float4*)W)[idx];
    uint2 hi, lo;
    cvt_split(v, hi, lo);
    ((uint2*)g_whi)[idx] = hi;
    ((uint2*)g_wlo)[idx] = lo;
}

// =====================================================================================
// Kernel 1: xp1 = x @ W_ih1^T + b_ih1 via mma.sync bf16 3-term split.
// R10 change: 512 threads, warp grid 4x4 (warp tile 32x32) -> 4 warps/SMSP latency
// hiding at UNCHANGED smem/CTA and 1 CTA/SM. Grid still 256.
// =====================================================================================
#define PITCH  80
#define NSTG   64
#define ATILE  (128 * PITCH)
#define BUFSZ  (4 * ATILE)
#define GSMEM  (512 + 2 * BUFSZ)  // 82432 B

// 512-thread staging: thread -> (row = tid>>2, qtr = tid&3): 8 fp32 cols per stage
__device__ __forceinline__ void stage_store(char* buf, uint32_t off,
                                            const float4* ra, uint4 rbh, uint4 rbl)
{
    char* Ahi = buf;
    char* Alo = buf + ATILE;
    char* Bhi = buf + 2 * ATILE;
    char* Blo = buf + 3 * ATILE;
#pragma unroll
    for (int f = 0; f < 2; ++f) {
        uint2 hi, lo;
        cvt_split(ra[f], hi, lo);
        *(uint2*)(Ahi + off + f * 8) = hi;
        *(uint2*)(Alo + off + f * 8) = lo;
    }
    *(uint4*)(Bhi + off) = rbh;
    *(uint4*)(Blo + off) = rbl;
}

__global__ void __launch_bounds__(512, 1) gemm_mma_kernel(
    const float* __restrict__ X, const float* __restrict__ bias)
{
    extern __shared__ __align__(16) char smem[];
    float* biasS = (float*)smem;
    char* bufb = smem + 512;
    const uint32_t sb = smem_u32(bufb);

    const int tid = threadIdx.x, lane = tid & 31, w = tid >> 5;
    const int wm = w & 3, wn = w >> 2;          // 4x4 warp grid, warp tile 32x32
    const int mBase = blockIdx.x * 128;

    if (tid < 128) biasS[tid] = bias[tid];

    // staging: (row, qtr) -> 8 fp32 cols per stage
    const int row = tid >> 2, qtr = tid & 3;
    const float* Arow = X + (size_t)(mBase + row) * D_IN + qtr * 8;
    const char* BhiG = (const char*)g_whi + (size_t)row * D_IN * 2 + qtr * 16;
    const char* BloG = (const char*)g_wlo + (size_t)row * D_IN * 2 + qtr * 16;
    const uint32_t sts_off = (uint32_t)(row * PITCH + qtr * 16);

    // ldmatrix lane offsets (proven pattern, n-extent now 32)
    const uint32_t aoff = (uint32_t)((wm * 32 + (lane & 15)) * PITCH + (lane >> 4) * 16);
    const uint32_t boff = (uint32_t)((wn * 32 + (lane & 7) + ((lane >> 4) & 1) * 8) * PITCH
                                     + ((lane >> 3) & 1) * 16);

    float4 acc[2][4];
#pragma unroll
    for (int mi = 0; mi < 2; ++mi)
#pragma unroll
        for (int ni = 0; ni < 4; ++ni) acc[mi][ni] = make_float4(0.f, 0.f, 0.f, 0.f);

    float4 ra[2];
    uint4 rbh, rbl;
    ra[0] = *(const float4*)(Arow);
    ra[1] = *(const float4*)(Arow + 4);
    rbh = *(const uint4*)(BhiG);
    rbl = *(const uint4*)(BloG);
    stage_store(bufb, sts_off, ra, rbh, rbl);
    __syncthreads();

    for (int i = 0; i < NSTG; ++i) {
        const int cur = i & 1;
        if (i + 1 < NSTG) {                     // prefetch next stage into regs
            const int ko = (i + 1) * 32;
            ra[0] = *(const float4*)(Arow + ko);
            ra[1] = *(const float4*)(Arow + ko + 4);
            rbh = *(const uint4*)(BhiG + ko * 2);
            rbl = *(const uint4*)(BloG + ko * 2);
        }

        const uint32_t Ahi = sb + cur * BUFSZ;
        const uint32_t Alo = Ahi + ATILE;
        const uint32_t Bhi = Ahi + 2 * ATILE;
        const uint32_t Blo = Ahi + 3 * ATILE;

#pragma unroll
        for (int kc = 0; kc < 2; ++kc) {        // two k16 chunks per stage
            const uint32_t kb = kc * 32;        // 16 bf16 = 32 B

            uint4 ah0 = ldsm4(Ahi + aoff + kb);
            uint4 ah1 = ldsm4(Ahi + aoff + 16 * PITCH + kb);
            uint4 bh0 = ldsm4(Bhi + boff + kb);
            uint4 bh1 = ldsm4(Bhi + boff + 16 * PITCH + kb);

            mma_bf16(acc[0][0], ah0, bh0.x, bh0.y);
            mma_bf16(acc[0][1], ah0, bh0.z, bh0.w);
            mma_bf16(acc[0][2], ah0, bh1.x, bh1.y);
            mma_bf16(acc[0][3], ah0, bh1.z, bh1.w);
            mma_bf16(acc[1][0], ah1, bh0.x, bh0.y);
            mma_bf16(acc[1][1], ah1, bh0.z, bh0.w);
            mma_bf16(acc[1][2], ah1, bh1.x, bh1.y);
            mma_bf16(acc[1][3], ah1, bh1.z, bh1.w);

            uint4 bl0 = ldsm4(Blo + boff + kb);
            uint4 bl1 = ldsm4(Blo + boff + 16 * PITCH + kb);

            mma_bf16(acc[0][0], ah0, bl0.x, bl0.y);
            mma_bf16(acc[0][1], ah0, bl0.z, bl0.w);
            mma_bf16(acc[0][2], ah0, bl1.x, bl1.y);
            mma_bf16(acc[0][3], ah0, bl1.z, bl1.w);
            mma_bf16(acc[1][0], ah1, bl0.x, bl0.y);
            mma_bf16(acc[1][1], ah1, bl0.z, bl0.w);
            mma_bf16(acc[1][2], ah1, bl1.x, bl1.y);
            mma_bf16(acc[1][3], ah1, bl1.z, bl1.w);

            uint4 al0 = ldsm4(Alo + aoff + kb);
            uint4 al1 = ldsm4(Alo + aoff + 16 * PITCH + kb);

            mma_bf16(acc[0][0], al0, bh0.x, bh0.y);
            mma_bf16(acc[0][1], al0, bh0.z, bh0.w);
            mma_bf16(acc[0][2], al0, bh1.x, bh1.y);
            mma_bf16(acc[0][3], al0, bh1.z, bh1.w);
            mma_bf16(acc[1][0], al1, bh0.x, bh0.y);
            mma_bf16(acc[1][1], al1, bh0.z, bh0.w);
            mma_bf16(acc[1][2], al1, bh1.x, bh1.y);
            mma_bf16(acc[1][3], al1, bh1.z, bh1.w);
        }

        if (i + 1 < NSTG) stage_store(bufb + (cur ^ 1) * BUFSZ, sts_off, ra, rbh, rbl);
        __syncthreads();
    }

    // epilogue: add bias, store fp32
    const int row0 = mBase + wm * 32 + (lane >> 2);
    const int cb = wn * 32 + (lane & 3) * 2;
#pragma unroll
    for (int mi = 0; mi < 2; ++mi)
#pragma unroll
        for (int ni = 0; ni < 4; ++ni) {
            const int r = row0 + mi * 16;
            const int c = cb + ni * 8;
            float2 v;
            v.x = acc[mi][ni].x + biasS[c];
            v.y = acc[mi][ni].y + biasS[c + 1];
            *(float2*)(g_xp1 + (size_t)r * H1 + c) = v;
            v.x = acc[mi][ni].z + biasS[c];
            v.y = acc[mi][ni].w + biasS[c + 1];
            *(float2*)(g_xp1 + (size_t)(r + 8) * H1 + c) = v;
        }
}

// =====================================================================================
// Kernel 2: warp-specialized pipelined dual-RNN scan + FC head (R6-proven, verbatim).
// =====================================================================================
__global__ void __launch_bounds__(256, 1) rnn_scan_kernel(
    const float* __restrict__ W_hh1, const float* __restrict__ b_hh1,
    const float* __restrict__ W_ih2, const float* __restrict__ W_hh2,
    const float* __restrict__ b_ih2, const float* __restrict__ b_hh2,
    const float* __restrict__ W_fc1, const float* __restrict__ b_fc1,
    const float* __restrict__ W_fc2, const float* __restrict__ b_fc2,
    float* __restrict__ out)
{
    __shared__ __align__(16) float h1buf[2][H1];
    __shared__ __align__(16) float h2buf[2][H2];

    const int tid = threadIdx.x;
    const int bb = blockIdx.x;

    if (tid < H1) h1buf[1][tid] = 0.f;   // h1(-1), read at t=0
    if (tid < H2) h2buf[1][tid] = 0.f;   // h2(-1)
    __syncthreads();

    if (tid < 128) {
        // ---------------- LAYER 1 ----------------
        const int i = tid;
        ull w1p[64];
#pragma unroll
        for (int k = 0; k < 64; ++k)
            w1p[k] = *(const ull*)(W_hh1 + i * H1 + 2 * k);
        const float bias = b_hh1[i];

        const float* xp = g_xp1 + (size_t)bb * TSEQ * H1;
        float xv = __ldg(xp + i);

        for (int t = 0; t < TSEQ; ++t) {
            const int s = t & 1;
            BAR_SYNC(3 + s, 256);        // EMPTY[s] (pre-armed by L2 for t=0,1)

            float xnext = 0.f;
            if (t < TSEQ - 1) xnext = __ldg(xp + (t + 1) * H1 + i);

            const ulonglong2* hp = (const ulonglong2*)h1buf[s ^ 1];
            ull a0 = 0, a1 = 0, a2 = 0, a3 = 0;
#pragma unroll
            for (int k = 0; k < 16; ++k) {
                ulonglong2 h01 = hp[2 * k];
                ulonglong2 h23 = hp[2 * k + 1];
                fma2(a0, w1p[4 * k + 0], h01.x);
                fma2(a1, w1p[4 * k + 1], h01.y);
                fma2(a2, w1p[4 * k + 2], h23.x);
                fma2(a3, w1p[4 * k + 3], h23.y);
            }
            ull s01, s23, sall;
            add2(s01, a0, a1);
            add2(s23, a2, a3);
            add2(sall, s01, s23);
            float dot = lo32(sall) + hi32(sall);

            h1buf[s][i] = fast_tanh(xv + bias + dot);
            BAR_ARRIVE(1 + s, 256);      // FULL[s]
            xv = xnext;
        }
    } else {
        // ---------------- LAYER 2 ----------------
        const int u = tid - 128;
        const int j = u >> 1, half = u & 1;

        BAR_ARRIVE(3, 256);              // pre-arm EMPTY[0]
        BAR_ARRIVE(4, 256);              // pre-arm EMPTY[1]

        ull wip[32];
#pragma unroll
        for (int k = 0; k < 32; ++k)
            wip[k] = *(const ull*)(W_ih2 + j * H1 + half * 64 + 2 * k);
        ull whp[16];
#pragma unroll
        for (int k = 0; k < 16; ++k)
            whp[k] = *(const ull*)(W_hh2 + j * H2 + half * 32 + 2 * k);
        const float bias2 = b_ih2[j] + b_hh2[j];

        for (int t = 0; t < TSEQ; ++t) {
            const int s = t & 1;
            BAR_SYNC(1 + s, 256);        // FULL[s]

            ulonglong2 hv[16];
            const ulonglong2* hp = (const ulonglong2*)(h1buf[s] + half * 64);
#pragma unroll
            for (int k = 0; k < 16; ++k) hv[k] = hp[k];
            BAR_ARRIVE(3 + s, 256);      // EMPTY[s]

            ull a0 = 0, a1 = 0, a2 = 0, a3 = 0;
#pragma unroll
            for (int k = 0; k < 8; ++k) {
                fma2(a0, wip[4 * k + 0], hv[2 * k].x);
                fma2(a1, wip[4 * k + 1], hv[2 * k].y);
                fma2(a2, wip[4 * k + 2], hv[2 * k + 1].x);
                fma2(a3, wip[4 * k + 3], hv[2 * k + 1].y);
            }
            const ulonglong2* gp = (const ulonglong2*)(h2buf[s ^ 1] + half * 32);
#pragma unroll
            for (int k = 0; k < 4; ++k) {
                ulonglong2 g01 = gp[2 * k];
                ulonglong2 g23 = gp[2 * k + 1];
                fma2(a0, whp[4 * k + 0], g01.x);
                fma2(a1, whp[4 * k + 1], g01.y);
                fma2(a2, whp[4 * k + 2], g23.x);
                fma2(a3, whp[4 * k + 3], g23.y);
            }
            ull s01, s23, sall;
            add2(s01, a0, a1);
            add2(s23, a2, a3);
            add2(sall, s01, s23);
            float d = lo32(sall) + hi32(sall);

            d += __shfl_xor_sync(0xffffffffu, d, 1);
            if (!half) h2buf[s][j] = fast_tanh(d + bias2);
        }

        BAR_SYNC(6, 128);                // L2-internal: final h2 visible for FC

        if (u < F1) {
            const float* hf = h2buf[(TSEQ - 1) & 1];
            float acc = b_fc1[u];
#pragma unroll
            for (int k = 0; k < H2; ++k) acc = fmaf(W_fc1[u * H2 + k], hf[k], acc);
            float r = fmaxf(acc, 0.f) * W_fc2[u];
#pragma unroll
            for (int sft = 16; sft > 0; sft >>= 1) r += __shfl_xor_sync(0xffffffffu, r, sft);
            if (u == 0) out[bb] = r + b_fc2[0];
        }
    }
}

// =====================================================================================
extern "C" void kernel_launch(void* const* d_in, const int* in_sizes, int n_in,
                              void* d_out, int out_size)
{
    const float* x     = (const float*)d_in[0];
    const float* W_ih1 = (const float*)d_in[1];
    const float* W_hh1 = (const float*)d_in[2];
    const float* b_ih1 = (const float*)d_in[3];
    const float* b_hh1 = (const float*)d_in[4];
    const float* W_ih2 = (const float*)d_in[5];
    const float* W_hh2 = (const float*)d_in[6];
    const float* b_ih2 = (const float*)d_in[7];
    const float* b_hh2 = (const float*)d_in[8];
    const float* W_fc1 = (const float*)d_in[9];
    const float* b_fc1 = (const float*)d_in[10];
    const float* W_fc2 = (const float*)d_in[11];
    const float* b_fc2 = (const float*)d_in[12];
    float* out = (float*)d_out;

    convert_w_kernel<<<256, 256>>>(W_ih1);
    cudaFuncSetAttribute(gemm_mma_kernel, cudaFuncAttributeMaxDynamicSharedMemorySize, GSMEM);
    gemm_mma_kernel<<<MTOT / 128, 512, GSMEM>>>(x, b_ih1);
    rnn_scan_kernel<<<BATCH, 256>>>(W_hh1, b_hh1, W_ih2, W_hh2, b_ih2, b_hh2,
                                    W_fc1, b_fc1, W_fc2, b_fc2, out);
}

// round 11
// speedup vs baseline: 1.6161x; 1.0888x over previous
#include <cuda_runtime.h>
#include <cuda_fp16.h>
#include <cstdint>

#define D_IN  2048
#define H1    128
#define H2    64
#define F1    32
#define BATCH 64
#define TSEQ  512
#define MTOT  (BATCH * TSEQ)   // 32768

typedef unsigned long long ull;

// ---- static device scratch (allocation-free) ----
__device__ float g_xp1[MTOT * H1];                          // 16 MB
__device__ __align__(16) unsigned short g_whi[H1 * D_IN];   // W_ih1 fp16 hi
__device__ __align__(16) unsigned short g_wlo[H1 * D_IN];   // W_ih1 fp16 lo (residual)

// ---------------- packed f32x2 helpers (scan) ----------------
__device__ __forceinline__ void fma2(ull &acc, ull a, ull b) {
    asm("fma.rn.f32x2 %0, %1, %2, %0;" : "+l"(acc) : "l"(a), "l"(b));
}
__device__ __forceinline__ void add2(ull &d, ull a, ull b) {
    asm("add.rn.f32x2 %0, %1, %2;" : "=l"(d) : "l"(a), "l"(b));
}
__device__ __forceinline__ float lo32(ull v) { return __uint_as_float((unsigned)v); }
__device__ __forceinline__ float hi32(ull v) { return __uint_as_float((unsigned)(v >> 32)); }

__device__ __forceinline__ float fast_tanh(float x) {
    float e = __expf(2.0f * x);
    return 1.0f - __fdividef(2.0f, e + 1.0f);
}

#define BAR_SYNC(id, n)   asm volatile("bar.sync %0, %1;"   :: "r"(id), "r"(n) : "memory")
#define BAR_ARRIVE(id, n) asm volatile("bar.arrive %0, %1;" :: "r"(id), "r"(n) : "memory")

__device__ __forceinline__ uint32_t smem_u32(const void* p) {
    uint32_t a;
    asm("{ .reg .u64 t; cvta.to.shared.u64 t, %1; cvt.u32.u64 %0, t; }" : "=r"(a) : "l"(p));
    return a;
}

// ---------------- mma.sync / ldmatrix primitives (legal on compute_103) ----------------
__device__ __forceinline__ void mma_f16(float4 &d, uint4 a, uint32_t b0, uint32_t b1) {
    asm volatile(
        "mma.sync.aligned.m16n8k16.row.col.f32.f16.f16.f32 "
        "{%0,%1,%2,%3}, {%4,%5,%6,%7}, {%8,%9}, {%0,%1,%2,%3};"
        : "+f"(d.x), "+f"(d.y), "+f"(d.z), "+f"(d.w)
        : "r"(a.x), "r"(a.y), "r"(a.z), "r"(a.w), "r"(b0), "r"(b1));
}
__device__ __forceinline__ uint4 ldsm4(uint32_t addr) {
    uint4 v;
    asm volatile("ldmatrix.sync.aligned.m8n8.x4.shared.b16 {%0,%1,%2,%3}, [%4];"
        : "=r"(v.x), "=r"(v.y), "=r"(v.z), "=r"(v.w) : "r"(addr));
    return v;
}

// pack 2 fp32 -> fp16x2 (lo = a, hi = b)
__device__ __forceinline__ uint32_t cvt_f16x2(float a, float b) {
    uint32_t r;
    asm("cvt.rn.f16x2.f32 %0, %1, %2;" : "=r"(r) : "f"(b), "f"(a));
    return r;
}

// =====================================================================================
// Kernel 0: pre-split W_ih1 (128x2048 fp32) into fp16 hi + fp16 residual lo globals.
// =====================================================================================
__global__ void __launch_bounds__(256, 1) convert_w_kernel(const float* __restrict__ W)
{
    int idx = blockIdx.x * 256 + threadIdx.x;        // 65536 float4s
    float4 v = ((const float4*)W)[idx];
    __half hx = __float2half_rn(v.x), hy = __float2half_rn(v.y);
    __half hz = __float2half_rn(v.z), hw = __float2half_rn(v.w);
    __half lx = __float2half_rn(v.x - __half2float(hx));
    __half ly = __float2half_rn(v.y - __half2float(hy));
    __half lz = __float2half_rn(v.z - __half2float(hz));
    __half lw = __float2half_rn(v.w - __half2float(hw));
    uint2 hi, lo;
    hi.x = (uint32_t)__half_as_ushort(hx) | ((uint32_t)__half_as_ushort(hy) << 16);
    hi.y = (uint32_t)__half_as_ushort(hz) | ((uint32_t)__half_as_ushort(hw) << 16);
    lo.x = (uint32_t)__half_as_ushort(lx) | ((uint32_t)__half_as_ushort(ly) << 16);
    lo.y = (uint32_t)__half_as_ushort(lz) | ((uint32_t)__half_as_ushort(lw) << 16);
    ((uint2*)g_whi)[idx] = hi;
    ((uint2*)g_wlo)[idx] = lo;
}

// =====================================================================================
// Kernel 1: xp1 = x @ W_ih1^T + b_ih1 via mma.sync fp16 2-TERM split:
//   D = A_f16 * B_hi + A_f16 * B_lo      (A rounded once; B pre-split exactly)
// CTA tile 128x128, 64 k-stages of 32 fp32 cols. 512 thr, 4x4 warp grid (32x32 tiles).
// Smem rows at 80B pitch (conflict-free ldmatrix). 16 MMAs + 6 ldsm per k16 pair.
// =====================================================================================
#define PITCH  80
#define NSTG   64
#define ATILE  (128 * PITCH)       // 10240 B per fp16 tile
#define BUFSZ  (3 * ATILE)         // A, B_hi, B_lo
#define GSMEM  (512 + 2 * BUFSZ)   // 61952 B

// 512-thread staging: thread -> (row = tid>>2, qtr = tid&3): 8 fp32 cols per stage
__device__ __forceinline__ void stage_store(char* buf, uint32_t off,
                                            float4 ra0, float4 ra1, uint4 rbh, uint4 rbl)
{
    uint4 a;
    a.x = cvt_f16x2(ra0.x, ra0.y);
    a.y = cvt_f16x2(ra0.z, ra0.w);
    a.z = cvt_f16x2(ra1.x, ra1.y);
    a.w = cvt_f16x2(ra1.z, ra1.w);
    *(uint4*)(buf + off)             = a;     // A
    *(uint4*)(buf + ATILE + off)     = rbh;   // B_hi
    *(uint4*)(buf + 2 * ATILE + off) = rbl;   // B_lo
}

__global__ void __launch_bounds__(512, 1) gemm_mma_kernel(
    const float* __restrict__ X, const float* __restrict__ bias)
{
    extern __shared__ __align__(16) char smem[];
    float* biasS = (float*)smem;
    char* bufb = smem + 512;
    const uint32_t sb = smem_u32(bufb);

    const int tid = threadIdx.x, lane = tid & 31, w = tid >> 5;
    const int wm = w & 3, wn = w >> 2;          // 4x4 warp grid, warp tile 32x32
    const int mBase = blockIdx.x * 128;

    if (tid < 128) biasS[tid] = bias[tid];

    // staging: (row, qtr) -> 8 fp32 cols per stage
    const int row = tid >> 2, qtr = tid & 3;
    const float* Arow = X + (size_t)(mBase + row) * D_IN + qtr * 8;
    const char* BhiG = (const char*)g_whi + (size_t)row * D_IN * 2 + qtr * 16;
    const char* BloG = (const char*)g_wlo + (size_t)row * D_IN * 2 + qtr * 16;
    const uint32_t sts_off = (uint32_t)(row * PITCH + qtr * 16);

    // ldmatrix lane offsets
    const uint32_t aoff = (uint32_t)((wm * 32 + (lane & 15)) * PITCH + (lane >> 4) * 16);
    const uint32_t boff = (uint32_t)((wn * 32 + (lane & 7) + ((lane >> 4) & 1) * 8) * PITCH
                                     + ((lane >> 3) & 1) * 16);

    float4 acc[2][4];
#pragma unroll
    for (int mi = 0; mi < 2; ++mi)
#pragma unroll
        for (int ni = 0; ni < 4; ++ni) acc[mi][ni] = make_float4(0.f, 0.f, 0.f, 0.f);

    float4 ra0, ra1;
    uint4 rbh, rbl;
    ra0 = *(const float4*)(Arow);
    ra1 = *(const float4*)(Arow + 4);
    rbh = *(const uint4*)(BhiG);
    rbl = *(const uint4*)(BloG);
    stage_store(bufb, sts_off, ra0, ra1, rbh, rbl);
    __syncthreads();

    for (int i = 0; i < NSTG; ++i) {
        const int cur = i & 1;
        if (i + 1 < NSTG) {                     // prefetch next stage into regs
            const int ko = (i + 1) * 32;
            ra0 = *(const float4*)(Arow + ko);
            ra1 = *(const float4*)(Arow + ko + 4);
            rbh = *(const uint4*)(BhiG + ko * 2);
            rbl = *(const uint4*)(BloG + ko * 2);
        }

        const uint32_t Asm = sb + cur * BUFSZ;
        const uint32_t Bhi = Asm + ATILE;
        const uint32_t Blo = Asm + 2 * ATILE;

#pragma unroll
        for (int kc = 0; kc < 2; ++kc) {        // two k16 chunks per stage
            const uint32_t kb = kc * 32;        // 16 fp16 = 32 B

            uint4 a0 = ldsm4(Asm + aoff + kb);
            uint4 a1 = ldsm4(Asm + aoff + 16 * PITCH + kb);
            uint4 bh0 = ldsm4(Bhi + boff + kb);
            uint4 bh1 = ldsm4(Bhi + boff + 16 * PITCH + kb);

            mma_f16(acc[0][0], a0, bh0.x, bh0.y);
            mma_f16(acc[0][1], a0, bh0.z, bh0.w);
            mma_f16(acc[0][2], a0, bh1.x, bh1.y);
            mma_f16(acc[0][3], a0, bh1.z, bh1.w);
            mma_f16(acc[1][0], a1, bh0.x, bh0.y);
            mma_f16(acc[1][1], a1, bh0.z, bh0.w);
            mma_f16(acc[1][2], a1, bh1.x, bh1.y);
            mma_f16(acc[1][3], a1, bh1.z, bh1.w);

            uint4 bl0 = ldsm4(Blo + boff + kb);
            uint4 bl1 = ldsm4(Blo + boff + 16 * PITCH + kb);

            mma_f16(acc[0][0], a0, bl0.x, bl0.y);
            mma_f16(acc[0][1], a0, bl0.z, bl0.w);
            mma_f16(acc[0][2], a0, bl1.x, bl1.y);
            mma_f16(acc[0][3], a0, bl1.z, bl1.w);
            mma_f16(acc[1][0], a1, bl0.x, bl0.y);
            mma_f16(acc[1][1], a1, bl0.z, bl0.w);
            mma_f16(acc[1][2], a1, bl1.x, bl1.y);
            mma_f16(acc[1][3], a1, bl1.z, bl1.w);
        }

        if (i + 1 < NSTG) stage_store(bufb + (cur ^ 1) * BUFSZ, sts_off, ra0, ra1, rbh, rbl);
        __syncthreads();
    }

    // epilogue: add bias, store fp32
    const int row0 = mBase + wm * 32 + (lane >> 2);
    const int cb = wn * 32 + (lane & 3) * 2;
#pragma unroll
    for (int mi = 0; mi < 2; ++mi)
#pragma unroll
        for (int ni = 0; ni < 4; ++ni) {
            const int r = row0 + mi * 16;
            const int c = cb + ni * 8;
            float2 v;
            v.x = acc[mi][ni].x + biasS[c];
            v.y = acc[mi][ni].y + biasS[c + 1];
            *(float2*)(g_xp1 + (size_t)r * H1 + c) = v;
            v.x = acc[mi][ni].z + biasS[c];
            v.y = acc[mi][ni].w + biasS[c + 1];
            *(float2*)(g_xp1 + (size_t)(r + 8) * H1 + c) = v;
        }
}

// =====================================================================================
// Kernel 2: warp-specialized pipelined dual-RNN scan + FC head (R6-proven, frozen).
// =====================================================================================
__global__ void __launch_bounds__(256, 1) rnn_scan_kernel(
    const float* __restrict__ W_hh1, const float* __restrict__ b_hh1,
    const float* __restrict__ W_ih2, const float* __restrict__ W_hh2,
    const float* __restrict__ b_ih2, const float* __restrict__ b_hh2,
    const float* __restrict__ W_fc1, const float* __restrict__ b_fc1,
    const float* __restrict__ W_fc2, const float* __restrict__ b_fc2,
    float* __restrict__ out)
{
    __shared__ __align__(16) float h1buf[2][H1];
    __shared__ __align__(16) float h2buf[2][H2];

    const int tid = threadIdx.x;
    const int bb = blockIdx.x;

    if (tid < H1) h1buf[1][tid] = 0.f;   // h1(-1), read at t=0
    if (tid < H2) h2buf[1][tid] = 0.f;   // h2(-1)
    __syncthreads();

    if (tid < 128) {
        // ---------------- LAYER 1 ----------------
        const int i = tid;
        ull w1p[64];
#pragma unroll
        for (int k = 0; k < 64; ++k)
            w1p[k] = *(const ull*)(W_hh1 + i * H1 + 2 * k);
        const float bias = b_hh1[i];

        const float* xp = g_xp1 + (size_t)bb * TSEQ * H1;
        float xv = __ldg(xp + i);

        for (int t = 0; t < TSEQ; ++t) {
            const int s = t & 1;
            BAR_SYNC(3 + s, 256);        // EMPTY[s] (pre-armed by L2 for t=0,1)

            float xnext = 0.f;
            if (t < TSEQ - 1) xnext = __ldg(xp + (t + 1) * H1 + i);

            const ulonglong2* hp = (const ulonglong2*)h1buf[s ^ 1];
            ull a0 = 0, a1 = 0, a2 = 0, a3 = 0;
#pragma unroll
            for (int k = 0; k < 16; ++k) {
                ulonglong2 h01 = hp[2 * k];
                ulonglong2 h23 = hp[2 * k + 1];
                fma2(a0, w1p[4 * k + 0], h01.x);
                fma2(a1, w1p[4 * k + 1], h01.y);
                fma2(a2, w1p[4 * k + 2], h23.x);
                fma2(a3, w1p[4 * k + 3], h23.y);
            }
            ull s01, s23, sall;
            add2(s01, a0, a1);
            add2(s23, a2, a3);
            add2(sall, s01, s23);
            float dot = lo32(sall) + hi32(sall);

            h1buf[s][i] = fast_tanh(xv + bias + dot);
            BAR_ARRIVE(1 + s, 256);      // FULL[s]
            xv = xnext;
        }
    } else {
        // ---------------- LAYER 2 ----------------
        const int u = tid - 128;
        const int j = u >> 1, half = u & 1;

        BAR_ARRIVE(3, 256);              // pre-arm EMPTY[0]
        BAR_ARRIVE(4, 256);              // pre-arm EMPTY[1]

        ull wip[32];
#pragma unroll
        for (int k = 0; k < 32; ++k)
            wip[k] = *(const ull*)(W_ih2 + j * H1 + half * 64 + 2 * k);
        ull whp[16];
#pragma unroll
        for (int k = 0; k < 16; ++k)
            whp[k] = *(const ull*)(W_hh2 + j * H2 + half * 32 + 2 * k);
        const float bias2 = b_ih2[j] + b_hh2[j];

        for (int t = 0; t < TSEQ; ++t) {
            const int s = t & 1;
            BAR_SYNC(1 + s, 256);        // FULL[s]

            ulonglong2 hv[16];
            const ulonglong2* hp = (const ulonglong2*)(h1buf[s] + half * 64);
#pragma unroll
            for (int k = 0; k < 16; ++k) hv[k] = hp[k];
            BAR_ARRIVE(3 + s, 256);      // EMPTY[s]

            ull a0 = 0, a1 = 0, a2 = 0, a3 = 0;
#pragma unroll
            for (int k = 0; k < 8; ++k) {
                fma2(a0, wip[4 * k + 0], hv[2 * k].x);
                fma2(a1, wip[4 * k + 1], hv[2 * k].y);
                fma2(a2, wip[4 * k + 2], hv[2 * k + 1].x);
                fma2(a3, wip[4 * k + 3], hv[2 * k + 1].y);
            }
            const ulonglong2* gp = (const ulonglong2*)(h2buf[s ^ 1] + half * 32);
#pragma unroll
            for (int k = 0; k < 4; ++k) {
                ulonglong2 g01 = gp[2 * k];
                ulonglong2 g23 = gp[2 * k + 1];
                fma2(a0, whp[4 * k + 0], g01.x);
                fma2(a1, whp[4 * k + 1], g01.y);
                fma2(a2, whp[4 * k + 2], g23.x);
                fma2(a3, whp[4 * k + 3], g23.y);
            }
            ull s01, s23, sall;
            add2(s01, a0, a1);
            add2(s23, a2, a3);
            add2(sall, s01, s23);
            float d = lo32(sall) + hi32(sall);

            d += __shfl_xor_sync(0xffffffffu, d, 1);
            if (!half) h2buf[s][j] = fast_tanh(d + bias2);
        }

        BAR_SYNC(6, 128);                // L2-internal: final h2 visible for FC

        if (u < F1) {
            const float* hf = h2buf[(TSEQ - 1) & 1];
            float acc = b_fc1[u];
#pragma unroll
            for (int k = 0; k < H2; ++k) acc = fmaf(W_fc1[u * H2 + k], hf[k], acc);
            float r = fmaxf(acc, 0.f) * W_fc2[u];
#pragma unroll
            for (int sft = 16; sft > 0; sft >>= 1) r += __shfl_xor_sync(0xffffffffu, r, sft);
            if (u == 0) out[bb] = r + b_fc2[0];
        }
    }
}

// =====================================================================================
extern "C" void kernel_launch(void* const* d_in, const int* in_sizes, int n_in,
                              void* d_out, int out_size)
{
    const float* x     = (const float*)d_in[0];
    const float* W_ih1 = (const float*)d_in[1];
    const float* W_hh1 = (const float*)d_in[2];
    const float* b_ih1 = (const float*)d_in[3];
    const float* b_hh1 = (const float*)d_in[4];
    const float* W_ih2 = (const float*)d_in[5];
    const float* W_hh2 = (const float*)d_in[6];
    const float* b_ih2 = (const float*)d_in[7];
    const float* b_hh2 = (const float*)d_in[8];
    const float* W_fc1 = (const float*)d_in[9];
    const float* b_fc1 = (const float*)d_in[10];
    const float* W_fc2 = (const float*)d_in[11];
    const float* b_fc2 = (const float*)d_in[12];
    float* out = (float*)d_out;

    convert_w_kernel<<<256, 256>>>(W_ih1);
    cudaFuncSetAttribute(gemm_mma_kernel, cudaFuncAttributeMaxDynamicSharedMemorySize, GSMEM);
    gemm_mma_kernel<<<MTOT / 128, 512, GSMEM>>>(x, b_ih1);
    rnn_scan_kernel<<<BATCH, 256>>>(W_hh1, b_hh1, W_ih2, W_hh2, b_ih2, b_hh2,
                                    W_fc1, b_fc1, W_fc2, b_fc2, out);
}

// round 12
// speedup vs baseline: 1.8713x; 1.1579x over previous
#include <cuda_runtime.h>
#include <cuda_fp16.h>
#include <cstdint>

#define D_IN  2048
#define H1    128
#define H2    64
#define F1    32
#define BATCH 64
#define TSEQ  512
#define MTOT  (BATCH * TSEQ)   // 32768

typedef unsigned long long ull;

// ---- static device scratch (allocation-free) ----
__device__ float g_xp1[MTOT * H1];                          // 16 MB
__device__ __align__(16) unsigned short g_whi[H1 * D_IN];   // W_ih1 fp16 hi
__device__ __align__(16) unsigned short g_wlo[H1 * D_IN];   // W_ih1 fp16 lo (residual)
__device__ int g_flag[BATCH * 4];                           // (bb, chunk) ready flags

// ---------------- packed f32x2 helpers (scan) ----------------
__device__ __forceinline__ void fma2(ull &acc, ull a, ull b) {
    asm("fma.rn.f32x2 %0, %1, %2, %0;" : "+l"(acc) : "l"(a), "l"(b));
}
__device__ __forceinline__ void add2(ull &d, ull a, ull b) {
    asm("add.rn.f32x2 %0, %1, %2;" : "=l"(d) : "l"(a), "l"(b));
}
__device__ __forceinline__ float lo32(ull v) { return __uint_as_float((unsigned)v); }
__device__ __forceinline__ float hi32(ull v) { return __uint_as_float((unsigned)(v >> 32)); }

__device__ __forceinline__ float fast_tanh(float x) {
    float e = __expf(2.0f * x);
    return 1.0f - __fdividef(2.0f, e + 1.0f);
}

#define BAR_SYNC(id, n)   asm volatile("bar.sync %0, %1;"   :: "r"(id), "r"(n) : "memory")
#define BAR_ARRIVE(id, n) asm volatile("bar.arrive %0, %1;" :: "r"(id), "r"(n) : "memory")

__device__ __forceinline__ uint32_t smem_u32(const void* p) {
    uint32_t a;
    asm("{ .reg .u64 t; cvta.to.shared.u64 t, %1; cvt.u32.u64 %0, t; }" : "=r"(a) : "l"(p));
    return a;
}

// acquire-spin on a ready flag (R7-proven mechanism)
__device__ __forceinline__ void wait_flag(const int* f) {
    unsigned v;
    while (true) {
        asm volatile("ld.acquire.gpu.b32 %0, [%1];" : "=r"(v) : "l"(f) : "memory");
        if (v) break;
        __nanosleep(200);
    }
}

// ---------------- mma.sync / ldmatrix primitives (legal on compute_103) ----------------
__device__ __forceinline__ void mma_f16(float4 &d, uint4 a, uint32_t b0, uint32_t b1) {
    asm volatile(
        "mma.sync.aligned.m16n8k16.row.col.f32.f16.f16.f32 "
        "{%0,%1,%2,%3}, {%4,%5,%6,%7}, {%8,%9}, {%0,%1,%2,%3};"
        : "+f"(d.x), "+f"(d.y), "+f"(d.z), "+f"(d.w)
        : "r"(a.x), "r"(a.y), "r"(a.z), "r"(a.w), "r"(b0), "r"(b1));
}
__device__ __forceinline__ uint4 ldsm4(uint32_t addr) {
    uint4 v;
    asm volatile("ldmatrix.sync.aligned.m8n8.x4.shared.b16 {%0,%1,%2,%3}, [%4];"
        : "=r"(v.x), "=r"(v.y), "=r"(v.z), "=r"(v.w) : "r"(addr));
    return v;
}
__device__ __forceinline__ uint32_t cvt_f16x2(float a, float b) {
    uint32_t r;
    asm("cvt.rn.f16x2.f32 %0, %1, %2;" : "=r"(r) : "f"(b), "f"(a));
    return r;
}

// =====================================================================================
// Kernel 0: pre-split W_ih1 into fp16 hi + residual lo globals; zero ready flags.
// =====================================================================================
__global__ void __launch_bounds__(256, 1) convert_w_kernel(const float* __restrict__ W)
{
    int idx = blockIdx.x * 256 + threadIdx.x;        // 65536 float4s
    if (blockIdx.x == 0) g_flag[threadIdx.x] = 0;    // 256 flags (reset every call)
    float4 v = ((const float4*)W)[idx];
    __half hx = __float2half_rn(v.x), hy = __float2half_rn(v.y);
    __half hz = __float2half_rn(v.z), hw = __float2half_rn(v.w);
    __half lx = __float2half_rn(v.x - __half2float(hx));
    __half ly = __float2half_rn(v.y - __half2float(hy));
    __half lz = __float2half_rn(v.z - __half2float(hz));
    __half lw = __float2half_rn(v.w - __half2float(hw));
    uint2 hi, lo;
    hi.x = (uint32_t)__half_as_ushort(hx) | ((uint32_t)__half_as_ushort(hy) << 16);
    hi.y = (uint32_t)__half_as_ushort(hz) | ((uint32_t)__half_as_ushort(hw) << 16);
    lo.x = (uint32_t)__half_as_ushort(lx) | ((uint32_t)__half_as_ushort(ly) << 16);
    lo.y = (uint32_t)__half_as_ushort(lz) | ((uint32_t)__half_as_ushort(lw) << 16);
    ((uint2*)g_whi)[idx] = hi;
    ((uint2*)g_wlo)[idx] = lo;
}

// =====================================================================================
// Fused kernel: blocks 0-63 = scan (one batch each); blocks 64-319 = GEMM tiles,
// CHUNK-MAJOR (g = bid-64 -> chunk cc = g>>6, batch bb = g&63) so chunk-0 tiles are
// the first GEMM blocks scheduled. 256 threads everywhere, 1 CTA/SM.
// =====================================================================================
#define PITCH  80
#define NSTG   64
#define ATILE  (128 * PITCH)       // 10240 B per fp16 tile
#define BUFSZ  (3 * ATILE)         // A, B_hi, B_lo
#define GSMEM  (512 + 2 * BUFSZ)   // 61952 B

// 256-thread staging: thread -> (row = tid>>1, half = tid&1): 16 fp32 cols per stage
__device__ __forceinline__ void stage_store(char* buf, uint32_t off,
                                            const float4* ra, const uint4* rbh, const uint4* rbl)
{
    uint4 a0, a1;
    a0.x = cvt_f16x2(ra[0].x, ra[0].y);
    a0.y = cvt_f16x2(ra[0].z, ra[0].w);
    a0.z = cvt_f16x2(ra[1].x, ra[1].y);
    a0.w = cvt_f16x2(ra[1].z, ra[1].w);
    a1.x = cvt_f16x2(ra[2].x, ra[2].y);
    a1.y = cvt_f16x2(ra[2].z, ra[2].w);
    a1.z = cvt_f16x2(ra[3].x, ra[3].y);
    a1.w = cvt_f16x2(ra[3].z, ra[3].w);
    *(uint4*)(buf + off)                  = a0;      // A
    *(uint4*)(buf + off + 16)             = a1;
    *(uint4*)(buf + ATILE + off)          = rbh[0];  // B_hi
    *(uint4*)(buf + ATILE + off + 16)     = rbh[1];
    *(uint4*)(buf + 2 * ATILE + off)      = rbl[0];  // B_lo
    *(uint4*)(buf + 2 * ATILE + off + 16) = rbl[1];
}

__device__ void gemm_body(int g, const float* __restrict__ X, const float* __restrict__ bias)
{
    extern __shared__ __align__(16) char smem[];
    float* biasS = (float*)smem;
    char* bufb = smem + 512;
    const uint32_t sb = smem_u32(bufb);

    const int tid = threadIdx.x, lane = tid & 31, w = tid >> 5;
    const int wm = w & 3, wn = w >> 2;          // 4x2 warp grid, warp tile 32x64
    const int cc = g >> 6, bb = g & 63;
    const int mBase = bb * TSEQ + cc * 128;

    if (tid < 128) biasS[tid] = bias[tid];

    const int row = tid >> 1, half = tid & 1;
    const float* Arow = X + (size_t)(mBase + row) * D_IN + half * 16;
    const char* BhiG = (const char*)g_whi + (size_t)row * D_IN * 2 + half * 32;
    const char* BloG = (const char*)g_wlo + (size_t)row * D_IN * 2 + half * 32;
    const uint32_t sts_off = (uint32_t)(row * PITCH + half * 32);

    const uint32_t aoff = (uint32_t)((wm * 32 + (lane & 15)) * PITCH + (lane >> 4) * 16);
    const uint32_t boff = (uint32_t)((wn * 64 + (lane & 7) + ((lane >> 4) & 1) * 8) * PITCH
                                     + ((lane >> 3) & 1) * 16);

    float4 acc[2][8];
#pragma unroll
    for (int mi = 0; mi < 2; ++mi)
#pragma unroll
        for (int ni = 0; ni < 8; ++ni) acc[mi][ni] = make_float4(0.f, 0.f, 0.f, 0.f);

    float4 ra[4];
    uint4 rbh[2], rbl[2];
#pragma unroll
    for (int f = 0; f < 4; ++f) ra[f] = *(const float4*)(Arow + f * 4);
    rbh[0] = *(const uint4*)(BhiG);
    rbh[1] = *(const uint4*)(BhiG + 16);
    rbl[0] = *(const uint4*)(BloG);
    rbl[1] = *(const uint4*)(BloG + 16);
    stage_store(bufb, sts_off, ra, rbh, rbl);
    __syncthreads();

    for (int i = 0; i < NSTG; ++i) {
        const int cur = i & 1;
        if (i + 1 < NSTG) {                     // prefetch next stage into regs
            const int ko = (i + 1) * 32;
#pragma unroll
            for (int f = 0; f < 4; ++f) ra[f] = *(const float4*)(Arow + ko + f * 4);
            rbh[0] = *(const uint4*)(BhiG + ko * 2);
            rbh[1] = *(const uint4*)(BhiG + ko * 2 + 16);
            rbl[0] = *(const uint4*)(BloG + ko * 2);
            rbl[1] = *(const uint4*)(BloG + ko * 2 + 16);
        }

        const uint32_t Asm = sb + cur * BUFSZ;
        const uint32_t Bhi = Asm + ATILE;
        const uint32_t Blo = Asm + 2 * ATILE;

#pragma unroll
        for (int kc = 0; kc < 2; ++kc) {
            const uint32_t kb = kc * 32;

            uint4 a0 = ldsm4(Asm + aoff + kb);
            uint4 a1 = ldsm4(Asm + aoff + 16 * PITCH + kb);
            uint4 bh0 = ldsm4(Bhi + boff + kb);
            uint4 bh1 = ldsm4(Bhi + boff + 16 * PITCH + kb);
            uint4 bh2 = ldsm4(Bhi + boff + 32 * PITCH + kb);
            uint4 bh3 = ldsm4(Bhi + boff + 48 * PITCH + kb);

            mma_f16(acc[0][0], a0, bh0.x, bh0.y);
            mma_f16(acc[0][1], a0, bh0.z, bh0.w);
            mma_f16(acc[0][2], a0, bh1.x, bh1.y);
            mma_f16(acc[0][3], a0, bh1.z, bh1.w);
            mma_f16(acc[0][4], a0, bh2.x, bh2.y);
            mma_f16(acc[0][5], a0, bh2.z, bh2.w);
            mma_f16(acc[0][6], a0, bh3.x, bh3.y);
            mma_f16(acc[0][7], a0, bh3.z, bh3.w);
            mma_f16(acc[1][0], a1, bh0.x, bh0.y);
            mma_f16(acc[1][1], a1, bh0.z, bh0.w);
            mma_f16(acc[1][2], a1, bh1.x, bh1.y);
            mma_f16(acc[1][3], a1, bh1.z, bh1.w);
            mma_f16(acc[1][4], a1, bh2.x, bh2.y);
            mma_f16(acc[1][5], a1, bh2.z, bh2.w);
            mma_f16(acc[1][6], a1, bh3.x, bh3.y);
            mma_f16(acc[1][7], a1, bh3.z, bh3.w);

            uint4 bl0 = ldsm4(Blo + boff + kb);
            uint4 bl1 = ldsm4(Blo + boff + 16 * PITCH + kb);
            uint4 bl2 = ldsm4(Blo + boff + 32 * PITCH + kb);
            uint4 bl3 = ldsm4(Blo + boff + 48 * PITCH + kb);

            mma_f16(acc[0][0], a0, bl0.x, bl0.y);
            mma_f16(acc[0][1], a0, bl0.z, bl0.w);
            mma_f16(acc[0][2], a0, bl1.x, bl1.y);
            mma_f16(acc[0][3], a0, bl1.z, bl1.w);
            mma_f16(acc[0][4], a0, bl2.x, bl2.y);
            mma_f16(acc[0][5], a0, bl2.z, bl2.w);
            mma_f16(acc[0][6], a0, bl3.x, bl3.y);
            mma_f16(acc[0][7], a0, bl3.z, bl3.w);
            mma_f16(acc[1][0], a1, bl0.x, bl0.y);
            mma_f16(acc[1][1], a1, bl0.z, bl0.w);
            mma_f16(acc[1][2], a1, bl1.x, bl1.y);
            mma_f16(acc[1][3], a1, bl1.z, bl1.w);
            mma_f16(acc[1][4], a1, bl2.x, bl2.y);
            mma_f16(acc[1][5], a1, bl2.z, bl2.w);
            mma_f16(acc[1][6], a1, bl3.x, bl3.y);
            mma_f16(acc[1][7], a1, bl3.z, bl3.w);
        }

        if (i + 1 < NSTG) stage_store(bufb + (cur ^ 1) * BUFSZ, sts_off, ra, rbh, rbl);
        __syncthreads();
    }

    // epilogue: add bias, store fp32
    const int row0 = mBase + wm * 32 + (lane >> 2);
    const int cb = wn * 64 + (lane & 3) * 2;
#pragma unroll
    for (int mi = 0; mi < 2; ++mi)
#pragma unroll
        for (int ni = 0; ni < 8; ++ni) {
            const int r = row0 + mi * 16;
            const int c = cb + ni * 8;
            float2 v;
            v.x = acc[mi][ni].x + biasS[c];
            v.y = acc[mi][ni].y + biasS[c + 1];
            *(float2*)(g_xp1 + (size_t)r * H1 + c) = v;
            v.x = acc[mi][ni].z + biasS[c];
            v.y = acc[mi][ni].w + biasS[c + 1];
            *(float2*)(g_xp1 + (size_t)(r + 8) * H1 + c) = v;
        }

    // publish: all CTA stores -> per-thread fence -> barrier -> release flag
    __threadfence();
    __syncthreads();
    if (tid == 0)
        asm volatile("st.release.gpu.b32 [%0], %1;"
                     :: "l"(&g_flag[bb * 4 + cc]), "r"(1) : "memory");
}

// ---- scan: R6/R11-proven pipelined design + 4 flag waits at chunk boundaries ----
__device__ void scan_body(
    const float* __restrict__ W_hh1, const float* __restrict__ b_hh1,
    const float* __restrict__ W_ih2, const float* __restrict__ W_hh2,
    const float* __restrict__ b_ih2, const float* __restrict__ b_hh2,
    const float* __restrict__ W_fc1, const float* __restrict__ b_fc1,
    const float* __restrict__ W_fc2, const float* __restrict__ b_fc2,
    float* __restrict__ out)
{
    __shared__ __align__(16) float h1buf[2][H1];
    __shared__ __align__(16) float h2buf[2][H2];

    const int tid = threadIdx.x;
    const int bb = blockIdx.x;

    if (tid < H1) h1buf[1][tid] = 0.f;   // h1(-1), read at t=0
    if (tid < H2) h2buf[1][tid] = 0.f;   // h2(-1)
    __syncthreads();

    if (tid < 128) {
        // ---------------- LAYER 1 ----------------
        const int i = tid;
        ull w1p[64];
#pragma unroll
        for (int k = 0; k < 64; ++k)
            w1p[k] = *(const ull*)(W_hh1 + i * H1 + 2 * k);
        const float bias = b_hh1[i];

        const float* xp = g_xp1 + (size_t)bb * TSEQ * H1;
        wait_flag(&g_flag[bb * 4]);      // chunk 0 ready
        float xv = __ldg(xp + i);

        for (int t = 0; t < TSEQ; ++t) {
            const int s = t & 1;
            BAR_SYNC(3 + s, 256);        // EMPTY[s] (pre-armed by L2 for t=0,1)

            float xnext = 0.f;
            if (t < TSEQ - 1) {
                if (((t + 1) & 127) == 0) wait_flag(&g_flag[bb * 4 + ((t + 1) >> 7)]);
                xnext = __ldg(xp + (t + 1) * H1 + i);
            }

            const ulonglong2* hp = (const ulonglong2*)h1buf[s ^ 1];
            ull a0 = 0, a1 = 0, a2 = 0, a3 = 0;
#pragma unroll
            for (int k = 0; k < 16; ++k) {
                ulonglong2 h01 = hp[2 * k];
                ulonglong2 h23 = hp[2 * k + 1];
                fma2(a0, w1p[4 * k + 0], h01.x);
                fma2(a1, w1p[4 * k + 1], h01.y);
                fma2(a2, w1p[4 * k + 2], h23.x);
                fma2(a3, w1p[4 * k + 3], h23.y);
            }
            ull s01, s23, sall;
            add2(s01, a0, a1);
            add2(s23, a2, a3);
            add2(sall, s01, s23);
            float dot = lo32(sall) + hi32(sall);

            h1buf[s][i] = fast_tanh(xv + bias + dot);
            BAR_ARRIVE(1 + s, 256);      // FULL[s]
            xv = xnext;
        }
    } else {
        // ---------------- LAYER 2 ----------------
        const int u = tid - 128;
        const int j = u >> 1, half = u & 1;

        BAR_ARRIVE(3, 256);              // pre-arm EMPTY[0]
        BAR_ARRIVE(4, 256);              // pre-arm EMPTY[1]

        ull wip[32];
#pragma unroll
        for (int k = 0; k < 32; ++k)
            wip[k] = *(const ull*)(W_ih2 + j * H1 + half * 64 + 2 * k);
        ull whp[16];
#pragma unroll
        for (int k = 0; k < 16; ++k)
            whp[k] = *(const ull*)(W_hh2 + j * H2 + half * 32 + 2 * k);
        const float bias2 = b_ih2[j] + b_hh2[j];

        for (int t = 0; t < TSEQ; ++t) {
            const int s = t & 1;
            BAR_SYNC(1 + s, 256);        // FULL[s]

            ulonglong2 hv[16];
            const ulonglong2* hp = (const ulonglong2*)(h1buf[s] + half * 64);
#pragma unroll
            for (int k = 0; k < 16; ++k) hv[k] = hp[k];
            BAR_ARRIVE(3 + s, 256);      // EMPTY[s]

            ull a0 = 0, a1 = 0, a2 = 0, a3 = 0;
#pragma unroll
            for (int k = 0; k < 8; ++k) {
                fma2(a0, wip[4 * k + 0], hv[2 * k].x);
                fma2(a1, wip[4 * k + 1], hv[2 * k].y);
                fma2(a2, wip[4 * k + 2], hv[2 * k + 1].x);
                fma2(a3, wip[4 * k + 3], hv[2 * k + 1].y);
            }
            const ulonglong2* gp = (const ulonglong2*)(h2buf[s ^ 1] + half * 32);
#pragma unroll
            for (int k = 0; k < 4; ++k) {
                ulonglong2 g01 = gp[2 * k];
                ulonglong2 g23 = gp[2 * k + 1];
                fma2(a0, whp[4 * k + 0], g01.x);
                fma2(a1, whp[4 * k + 1], g01.y);
                fma2(a2, whp[4 * k + 2], g23.x);
                fma2(a3, whp[4 * k + 3], g23.y);
            }
            ull s01, s23, sall;
            add2(s01, a0, a1);
            add2(s23, a2, a3);
            add2(sall, s01, s23);
            float d = lo32(sall) + hi32(sall);

            d += __shfl_xor_sync(0xffffffffu, d, 1);
            if (!half) h2buf[s][j] = fast_tanh(d + bias2);
        }

        BAR_SYNC(6, 128);                // L2-internal: final h2 visible for FC

        if (u < F1) {
            const float* hf = h2buf[(TSEQ - 1) & 1];
            float acc = b_fc1[u];
#pragma unroll
            for (int k = 0; k < H2; ++k) acc = fmaf(W_fc1[u * H2 + k], hf[k], acc);
            float r = fmaxf(acc, 0.f) * W_fc2[u];
#pragma unroll
            for (int sft = 16; sft > 0; sft >>= 1) r += __shfl_xor_sync(0xffffffffu, r, sft);
            if (u == 0) out[bb] = r + b_fc2[0];
        }
    }
}

__global__ void __launch_bounds__(256, 1) fused_kernel(
    const float* __restrict__ X, const float* __restrict__ b_ih1,
    const float* __restrict__ W_hh1, const float* __restrict__ b_hh1,
    const float* __restrict__ W_ih2, const float* __restrict__ W_hh2,
    const float* __restrict__ b_ih2, const float* __restrict__ b_hh2,
    const float* __restrict__ W_fc1, const float* __restrict__ b_fc1,
    const float* __restrict__ W_fc2, const float* __restrict__ b_fc2,
    float* __restrict__ out)
{
    if (blockIdx.x >= 64) {
        gemm_body((int)blockIdx.x - 64, X, b_ih1);
    } else {
        scan_body(W_hh1, b_hh1, W_ih2, W_hh2, b_ih2, b_hh2,
                  W_fc1, b_fc1, W_fc2, b_fc2, out);
    }
}

// =====================================================================================
extern "C" void kernel_launch(void* const* d_in, const int* in_sizes, int n_in,
                              void* d_out, int out_size)
{
    const float* x     = (const float*)d_in[0];
    const float* W_ih1 = (const float*)d_in[1];
    const float* W_hh1 = (const float*)d_in[2];
    const float* b_ih1 = (const float*)d_in[3];
    const float* b_hh1 = (const float*)d_in[4];
    const float* W_ih2 = (const float*)d_in[5];
    const float* W_hh2 = (const float*)d_in[6];
    const float* b_ih2 = (const float*)d_in[7];
    const float* b_hh2 = (const float*)d_in[8];
    const float* W_fc1 = (const float*)d_in[9];
    const float* b_fc1 = (const float*)d_in[10];
    const float* W_fc2 = (const float*)d_in[11];
    const float* b_fc2 = (const float*)d_in[12];
    float* out = (float*)d_out;

    convert_w_kernel<<<256, 256>>>(W_ih1);
    cudaFuncSetAttribute(fused_kernel, cudaFuncAttributeMaxDynamicSharedMemorySize, GSMEM);
    fused_kernel<<<64 + MTOT / 128, 256, GSMEM>>>(
        x, b_ih1, W_hh1, b_hh1, W_ih2, W_hh2, b_ih2, b_hh2,
        W_fc1, b_fc1, W_fc2, b_fc2, out);
}

// round 13
// speedup vs baseline: 1.9787x; 1.0574x over previous
#include <cuda_runtime.h>
#include <cuda_fp16.h>
#include <cstdint>

#define D_IN  2048
#define H1    128
#define H2    64
#define F1    32
#define BATCH 64
#define TSEQ  512
#define MTOT  (BATCH * TSEQ)   // 32768

typedef unsigned long long ull;

// ---- static device scratch (allocation-free) ----
__device__ float g_xp1[MTOT * H1];                          // 16 MB
__device__ __align__(16) unsigned short g_whi[H1 * D_IN];   // W_ih1 fp16
__device__ int g_flag[BATCH * 4];                           // (bb, chunk) ready flags

// ---------------- packed f32x2 helpers (scan) ----------------
__device__ __forceinline__ void fma2(ull &acc, ull a, ull b) {
    asm("fma.rn.f32x2 %0, %1, %2, %0;" : "+l"(acc) : "l"(a), "l"(b));
}
__device__ __forceinline__ void add2(ull &d, ull a, ull b) {
    asm("add.rn.f32x2 %0, %1, %2;" : "=l"(d) : "l"(a), "l"(b));
}
__device__ __forceinline__ float lo32(ull v) { return __uint_as_float((unsigned)v); }
__device__ __forceinline__ float hi32(ull v) { return __uint_as_float((unsigned)(v >> 32)); }

__device__ __forceinline__ float fast_tanh(float x) {
    float e = __expf(2.0f * x);
    return 1.0f - __fdividef(2.0f, e + 1.0f);
}

#define BAR_SYNC(id, n)   asm volatile("bar.sync %0, %1;"   :: "r"(id), "r"(n) : "memory")
#define BAR_ARRIVE(id, n) asm volatile("bar.arrive %0, %1;" :: "r"(id), "r"(n) : "memory")

__device__ __forceinline__ uint32_t smem_u32(const void* p) {
    uint32_t a;
    asm("{ .reg .u64 t; cvta.to.shared.u64 t, %1; cvt.u32.u64 %0, t; }" : "=r"(a) : "l"(p));
    return a;
}

// acquire-spin on a ready flag
__device__ __forceinline__ void wait_flag(const int* f) {
    unsigned v;
    while (true) {
        asm volatile("ld.acquire.gpu.b32 %0, [%1];" : "=r"(v) : "l"(f) : "memory");
        if (v) break;
        __nanosleep(200);
    }
}

// ---------------- mma.sync / ldmatrix primitives (legal on compute_103) ----------------
__device__ __forceinline__ void mma_f16(float4 &d, uint4 a, uint32_t b0, uint32_t b1) {
    asm volatile(
        "mma.sync.aligned.m16n8k16.row.col.f32.f16.f16.f32 "
        "{%0,%1,%2,%3}, {%4,%5,%6,%7}, {%8,%9}, {%0,%1,%2,%3};"
        : "+f"(d.x), "+f"(d.y), "+f"(d.z), "+f"(d.w)
        : "r"(a.x), "r"(a.y), "r"(a.z), "r"(a.w), "r"(b0), "r"(b1));
}
__device__ __forceinline__ uint4 ldsm4(uint32_t addr) {
    uint4 v;
    asm volatile("ldmatrix.sync.aligned.m8n8.x4.shared.b16 {%0,%1,%2,%3}, [%4];"
        : "=r"(v.x), "=r"(v.y), "=r"(v.z), "=r"(v.w) : "r"(addr));
    return v;
}
__device__ __forceinline__ uint32_t cvt_f16x2(float a, float b) {
    uint32_t r;
    asm("cvt.rn.f16x2.f32 %0, %1, %2;" : "=r"(r) : "f"(b), "f"(a));
    return r;
}

// =====================================================================================
// Kernel 0: convert W_ih1 to fp16 (single rounding); zero ready flags.
// =====================================================================================
__global__ void __launch_bounds__(256, 1) convert_w_kernel(const float* __restrict__ W)
{
    int idx = blockIdx.x * 256 + threadIdx.x;        // 65536 float4s
    if (blockIdx.x == 0) g_flag[threadIdx.x] = 0;    // 256 flags (reset every call)
    float4 v = ((const float4*)W)[idx];
    uint2 hi;
    hi.x = cvt_f16x2(v.x, v.y);
    hi.y = cvt_f16x2(v.z, v.w);
    ((uint2*)g_whi)[idx] = hi;
}

// =====================================================================================
// Fused kernel: blocks 0-63 = scan (one batch each); blocks 64-319 = GEMM tiles,
// CHUNK-MAJOR (g = bid-64 -> chunk cc = g>>6, batch bb = g&63).
// GEMM is pure fp16 1-term: D = A_f16 * B_f16 (8 MMAs + 4 ldsm per k16 chunk).
// =====================================================================================
#define PITCH  80
#define NSTG   64
#define ATILE  (128 * PITCH)       // 10240 B per fp16 tile
#define BUFSZ  (2 * ATILE)         // A, B
#define GSMEM  (512 + 2 * BUFSZ)   // 41472 B

// 256-thread staging: thread -> (row = tid>>1, half = tid&1): 16 fp32 cols per stage
__device__ __forceinline__ void stage_store(char* buf, uint32_t off,
                                            const float4* ra, const uint4* rb)
{
    uint4 a0, a1;
    a0.x = cvt_f16x2(ra[0].x, ra[0].y);
    a0.y = cvt_f16x2(ra[0].z, ra[0].w);
    a0.z = cvt_f16x2(ra[1].x, ra[1].y);
    a0.w = cvt_f16x2(ra[1].z, ra[1].w);
    a1.x = cvt_f16x2(ra[2].x, ra[2].y);
    a1.y = cvt_f16x2(ra[2].z, ra[2].w);
    a1.z = cvt_f16x2(ra[3].x, ra[3].y);
    a1.w = cvt_f16x2(ra[3].z, ra[3].w);
    *(uint4*)(buf + off)              = a0;     // A
    *(uint4*)(buf + off + 16)         = a1;
    *(uint4*)(buf + ATILE + off)      = rb[0];  // B
    *(uint4*)(buf + ATILE + off + 16) = rb[1];
}

__device__ void gemm_body(int g, const float* __restrict__ X, const float* __restrict__ bias)
{
    extern __shared__ __align__(16) char smem[];
    float* biasS = (float*)smem;
    char* bufb = smem + 512;
    const uint32_t sb = smem_u32(bufb);

    const int tid = threadIdx.x, lane = tid & 31, w = tid >> 5;
    const int wm = w & 3, wn = w >> 2;          // 4x2 warp grid, warp tile 32x64
    const int cc = g >> 6, bb = g & 63;
    const int mBase = bb * TSEQ + cc * 128;

    if (tid < 128) biasS[tid] = bias[tid];

    const int row = tid >> 1, half = tid & 1;
    const float* Arow = X + (size_t)(mBase + row) * D_IN + half * 16;
    const char* BG = (const char*)g_whi + (size_t)row * D_IN * 2 + half * 32;
    const uint32_t sts_off = (uint32_t)(row * PITCH + half * 32);

    const uint32_t aoff = (uint32_t)((wm * 32 + (lane & 15)) * PITCH + (lane >> 4) * 16);
    const uint32_t boff = (uint32_t)((wn * 64 + (lane & 7) + ((lane >> 4) & 1) * 8) * PITCH
                                     + ((lane >> 3) & 1) * 16);

    float4 acc[2][8];
#pragma unroll
    for (int mi = 0; mi < 2; ++mi)
#pragma unroll
        for (int ni = 0; ni < 8; ++ni) acc[mi][ni] = make_float4(0.f, 0.f, 0.f, 0.f);

    float4 ra[4];
    uint4 rb[2];
#pragma unroll
    for (int f = 0; f < 4; ++f) ra[f] = *(const float4*)(Arow + f * 4);
    rb[0] = *(const uint4*)(BG);
    rb[1] = *(const uint4*)(BG + 16);
    stage_store(bufb, sts_off, ra, rb);
    __syncthreads();

    for (int i = 0; i < NSTG; ++i) {
        const int cur = i & 1;
        if (i + 1 < NSTG) {                     // prefetch next stage into regs
            const int ko = (i + 1) * 32;
#pragma unroll
            for (int f = 0; f < 4; ++f) ra[f] = *(const float4*)(Arow + ko + f * 4);
            rb[0] = *(const uint4*)(BG + ko * 2);
            rb[1] = *(const uint4*)(BG + ko * 2 + 16);
        }

        const uint32_t Asm = sb + cur * BUFSZ;
        const uint32_t Bsm = Asm + ATILE;

#pragma unroll
        for (int kc = 0; kc < 2; ++kc) {
            const uint32_t kb = kc * 32;

            uint4 a0 = ldsm4(Asm + aoff + kb);
            uint4 a1 = ldsm4(Asm + aoff + 16 * PITCH + kb);
            uint4 b0 = ldsm4(Bsm + boff + kb);
            uint4 b1 = ldsm4(Bsm + boff + 16 * PITCH + kb);
            uint4 b2 = ldsm4(Bsm + boff + 32 * PITCH + kb);
            uint4 b3 = ldsm4(Bsm + boff + 48 * PITCH + kb);

            mma_f16(acc[0][0], a0, b0.x, b0.y);
            mma_f16(acc[0][1], a0, b0.z, b0.w);
            mma_f16(acc[0][2], a0, b1.x, b1.y);
            mma_f16(acc[0][3], a0, b1.z, b1.w);
            mma_f16(acc[0][4], a0, b2.x, b2.y);
            mma_f16(acc[0][5], a0, b2.z, b2.w);
            mma_f16(acc[0][6], a0, b3.x, b3.y);
            mma_f16(acc[0][7], a0, b3.z, b3.w);
            mma_f16(acc[1][0], a1, b0.x, b0.y);
            mma_f16(acc[1][1], a1, b0.z, b0.w);
            mma_f16(acc[1][2], a1, b1.x, b1.y);
            mma_f16(acc[1][3], a1, b1.z, b1.w);
            mma_f16(acc[1][4], a1, b2.x, b2.y);
            mma_f16(acc[1][5], a1, b2.z, b2.w);
            mma_f16(acc[1][6], a1, b3.x, b3.y);
            mma_f16(acc[1][7], a1, b3.z, b3.w);
        }

        if (i + 1 < NSTG) stage_store(bufb + (cur ^ 1) * BUFSZ, sts_off, ra, rb);
        __syncthreads();
    }

    // epilogue: add bias, store fp32
    const int row0 = mBase + wm * 32 + (lane >> 2);
    const int cb = wn * 64 + (lane & 3) * 2;
#pragma unroll
    for (int mi = 0; mi < 2; ++mi)
#pragma unroll
        for (int ni = 0; ni < 8; ++ni) {
            const int r = row0 + mi * 16;
            const int c = cb + ni * 8;
            float2 v;
            v.x = acc[mi][ni].x + biasS[c];
            v.y = acc[mi][ni].y + biasS[c + 1];
            *(float2*)(g_xp1 + (size_t)r * H1 + c) = v;
            v.x = acc[mi][ni].z + biasS[c];
            v.y = acc[mi][ni].w + biasS[c + 1];
            *(float2*)(g_xp1 + (size_t)(r + 8) * H1 + c) = v;
        }

    // publish: all CTA stores -> per-thread fence -> barrier -> release flag
    __threadfence();
    __syncthreads();
    if (tid == 0)
        asm volatile("st.release.gpu.b32 [%0], %1;"
                     :: "l"(&g_flag[bb * 4 + cc]), "r"(1) : "memory");
}

// ---- scan: R6/R11-proven pipelined design + flag waits at chunk boundaries ----
__device__ void scan_body(
    const float* __restrict__ W_hh1, const float* __restrict__ b_hh1,
    const float* __restrict__ W_ih2, const float* __restrict__ W_hh2,
    const float* __restrict__ b_ih2, const float* __restrict__ b_hh2,
    const float* __restrict__ W_fc1, const float* __restrict__ b_fc1,
    const float* __restrict__ W_fc2, const float* __restrict__ b_fc2,
    float* __restrict__ out)
{
    __shared__ __align__(16) float h1buf[2][H1];
    __shared__ __align__(16) float h2buf[2][H2];

    const int tid = threadIdx.x;
    const int bb = blockIdx.x;

    if (tid < H1) h1buf[1][tid] = 0.f;   // h1(-1), read at t=0
    if (tid < H2) h2buf[1][tid] = 0.f;   // h2(-1)
    __syncthreads();

    if (tid < 128) {
        // ---------------- LAYER 1 ----------------
        const int i = tid;
        ull w1p[64];
#pragma unroll
        for (int k = 0; k < 64; ++k)
            w1p[k] = *(const ull*)(W_hh1 + i * H1 + 2 * k);
        const float bias = b_hh1[i];

        const float* xp = g_xp1 + (size_t)bb * TSEQ * H1;
        wait_flag(&g_flag[bb * 4]);      // chunk 0 ready
        float xv = __ldg(xp + i);

        for (int t = 0; t < TSEQ; ++t) {
            const int s = t & 1;
            BAR_SYNC(3 + s, 256);        // EMPTY[s] (pre-armed by L2 for t=0,1)

            float xnext = 0.f;
            if (t < TSEQ - 1) {
                if (((t + 1) & 127) == 0) wait_flag(&g_flag[bb * 4 + ((t + 1) >> 7)]);
                xnext = __ldg(xp + (t + 1) * H1 + i);
            }

            const ulonglong2* hp = (const ulonglong2*)h1buf[s ^ 1];
            ull a0 = 0, a1 = 0, a2 = 0, a3 = 0;
#pragma unroll
            for (int k = 0; k < 16; ++k) {
                ulonglong2 h01 = hp[2 * k];
                ulonglong2 h23 = hp[2 * k + 1];
                fma2(a0, w1p[4 * k + 0], h01.x);
                fma2(a1, w1p[4 * k + 1], h01.y);
                fma2(a2, w1p[4 * k + 2], h23.x);
                fma2(a3, w1p[4 * k + 3], h23.y);
            }
            ull s01, s23, sall;
            add2(s01, a0, a1);
            add2(s23, a2, a3);
            add2(sall, s01, s23);
            float dot = lo32(sall) + hi32(sall);

            h1buf[s][i] = fast_tanh(xv + bias + dot);
            BAR_ARRIVE(1 + s, 256);      // FULL[s]
            xv = xnext;
        }
    } else {
        // ---------------- LAYER 2 ----------------
        const int u = tid - 128;
        const int j = u >> 1, half = u & 1;

        BAR_ARRIVE(3, 256);              // pre-arm EMPTY[0]
        BAR_ARRIVE(4, 256);              // pre-arm EMPTY[1]

        ull wip[32];
#pragma unroll
        for (int k = 0; k < 32; ++k)
            wip[k] = *(const ull*)(W_ih2 + j * H1 + half * 64 + 2 * k);
        ull whp[16];
#pragma unroll
        for (int k = 0; k < 16; ++k)
            whp[k] = *(const ull*)(W_hh2 + j * H2 + half * 32 + 2 * k);
        const float bias2 = b_ih2[j] + b_hh2[j];

        for (int t = 0; t < TSEQ; ++t) {
            const int s = t & 1;
            BAR_SYNC(1 + s, 256);        // FULL[s]

            ulonglong2 hv[16];
            const ulonglong2* hp = (const ulonglong2*)(h1buf[s] + half * 64);
#pragma unroll
            for (int k = 0; k < 16; ++k) hv[k] = hp[k];
            BAR_ARRIVE(3 + s, 256);      // EMPTY[s]

            ull a0 = 0, a1 = 0, a2 = 0, a3 = 0;
#pragma unroll
            for (int k = 0; k < 8; ++k) {
                fma2(a0, wip[4 * k + 0], hv[2 * k].x);
                fma2(a1, wip[4 * k + 1], hv[2 * k].y);
                fma2(a2, wip[4 * k + 2], hv[2 * k + 1].x);
                fma2(a3, wip[4 * k + 3], hv[2 * k + 1].y);
            }
            const ulonglong2* gp = (const ulonglong2*)(h2buf[s ^ 1] + half * 32);
#pragma unroll
            for (int k = 0; k < 4; ++k) {
                ulonglong2 g01 = gp[2 * k];
                ulonglong2 g23 = gp[2 * k + 1];
                fma2(a0, whp[4 * k + 0], g01.x);
                fma2(a1, whp[4 * k + 1], g01.y);
                fma2(a2, whp[4 * k + 2], g23.x);
                fma2(a3, whp[4 * k + 3], g23.y);
            }
            ull s01, s23, sall;
            add2(s01, a0, a1);
            add2(s23, a2, a3);
            add2(sall, s01, s23);
            float d = lo32(sall) + hi32(sall);

            d += __shfl_xor_sync(0xffffffffu, d, 1);
            if (!half) h2buf[s][j] = fast_tanh(d + bias2);
        }

        BAR_SYNC(6, 128);                // L2-internal: final h2 visible for FC

        if (u < F1) {
            const float* hf = h2buf[(TSEQ - 1) & 1];
            float acc = b_fc1[u];
#pragma unroll
            for (int k = 0; k < H2; ++k) acc = fmaf(W_fc1[u * H2 + k], hf[k], acc);
            float r = fmaxf(acc, 0.f) * W_fc2[u];
#pragma unroll
            for (int sft = 16; sft > 0; sft >>= 1) r += __shfl_xor_sync(0xffffffffu, r, sft);
            if (u == 0) out[bb] = r + b_fc2[0];
        }
    }
}

__global__ void __launch_bounds__(256, 1) fused_kernel(
    const float* __restrict__ X, const float* __restrict__ b_ih1,
    const float* __restrict__ W_hh1, const float* __restrict__ b_hh1,
    const float* __restrict__ W_ih2, const float* __restrict__ W_hh2,
    const float* __restrict__ b_ih2, const float* __restrict__ b_hh2,
    const float* __restrict__ W_fc1, const float* __restrict__ b_fc1,
    const float* __restrict__ W_fc2, const float* __restrict__ b_fc2,
    float* __restrict__ out)
{
    if (blockIdx.x >= 64) {
        gemm_body((int)blockIdx.x - 64, X, b_ih1);
    } else {
        scan_body(W_hh1, b_hh1, W_ih2, W_hh2, b_ih2, b_hh2,
                  W_fc1, b_fc1, W_fc2, b_fc2, out);
    }
}

// =====================================================================================
extern "C" void kernel_launch(void* const* d_in, const int* in_sizes, int n_in,
                              void* d_out, int out_size)
{
    const float* x     = (const float*)d_in[0];
    const float* W_ih1 = (const float*)d_in[1];
    const float* W_hh1 = (const float*)d_in[2];
    const float* b_ih1 = (const float*)d_in[3];
    const float* b_hh1 = (const float*)d_in[4];
    const float* W_ih2 = (const float*)d_in[5];
    const float* W_hh2 = (const float*)d_in[6];
    const float* b_ih2 = (const float*)d_in[7];
    const float* b_hh2 = (const float*)d_in[8];
    const float* W_fc1 = (const float*)d_in[9];
    const float* b_fc1 = (const float*)d_in[10];
    const float* W_fc2 = (const float*)d_in[11];
    const float* b_fc2 = (const float*)d_in[12];
    float* out = (float*)d_out;

    convert_w_kernel<<<256, 256>>>(W_ih1);
    cudaFuncSetAttribute(fused_kernel, cudaFuncAttributeMaxDynamicSharedMemorySize, GSMEM);
    fused_kernel<<<64 + MTOT / 128, 256, GSMEM>>>(
        x, b_ih1, W_hh1, b_hh1, W_ih2, W_hh2, b_ih2, b_hh2,
        W_fc1, b_fc1, W_fc2, b_fc2, out);
}